// round 13
// baseline (speedup 1.0000x reference)
#include <cuda_runtime.h>
#include <cuda_bf16.h>
#include <cstdint>

// Problem constants
#define MTOK   62400      // B*S*N
#define DMODEL 256
#define FDIM   2048
#define NHEAD  8
#define HD     32
#define NNODE  325
#define NPAD   336        // 21 * 16
#define NKT    21

#define TSLICE ((size_t)MTOK * DMODEL)     // 15,974,400
#define FSLICE ((size_t)MTOK * FDIM)       // 127,795,200
__device__ float g_scratch[7 * TSLICE + FSLICE];

typedef __nv_bfloat16 bf;

// ---------------------------------------------------------------------------
// PTX helpers
// ---------------------------------------------------------------------------
__device__ __forceinline__ uint32_t smem_u32(const void* p) {
    uint32_t a;
    asm("{ .reg .u64 t; cvta.to.shared.u64 t, %1; cvt.u32.u64 %0, t; }" : "=r"(a) : "l"(p));
    return a;
}
__device__ __forceinline__ void ldsm_x4(uint32_t* r, uint32_t addr) {
    asm volatile("ldmatrix.sync.aligned.m8n8.x4.shared.b16 {%0,%1,%2,%3}, [%4];"
                 : "=r"(r[0]), "=r"(r[1]), "=r"(r[2]), "=r"(r[3]) : "r"(addr));
}
__device__ __forceinline__ void ldsm_x4_t(uint32_t* r, uint32_t addr) {
    asm volatile("ldmatrix.sync.aligned.m8n8.x4.trans.shared.b16 {%0,%1,%2,%3}, [%4];"
                 : "=r"(r[0]), "=r"(r[1]), "=r"(r[2]), "=r"(r[3]) : "r"(addr));
}
__device__ __forceinline__ void mma_bf16(float* d, const uint32_t* a, const uint32_t* b) {
    asm volatile("mma.sync.aligned.m16n8k16.row.col.f32.bf16.bf16.f32 "
                 "{%0,%1,%2,%3}, {%4,%5,%6,%7}, {%8,%9}, {%0,%1,%2,%3};"
                 : "+f"(d[0]), "+f"(d[1]), "+f"(d[2]), "+f"(d[3])
                 : "r"(a[0]), "r"(a[1]), "r"(a[2]), "r"(a[3]), "r"(b[0]), "r"(b[1]));
}
__device__ __forceinline__ void cp16(uint32_t dst, const void* src, bool pred) {
    int sz = pred ? 16 : 0;
    asm volatile("cp.async.cg.shared.global [%0], [%1], 16, %2;"
                 :: "r"(dst), "l"(src), "r"(sz));
}
__device__ __forceinline__ void cp_commit() {
    asm volatile("cp.async.commit_group;" ::: "memory");
}
__device__ __forceinline__ void cp_wait2() {
    asm volatile("cp.async.wait_group 2;" ::: "memory");
}
__device__ __forceinline__ void split2(float x, float y, uint32_t& hi, uint32_t& lo) {
    __nv_bfloat162 h = __floats2bfloat162_rn(x, y);
    float2 hf = __bfloat1622float2(h);
    __nv_bfloat162 l = __floats2bfloat162_rn(x - hf.x, y - hf.y);
    hi = *reinterpret_cast<uint32_t*>(&h);
    lo = *reinterpret_cast<uint32_t*>(&l);
}

// ---------------------------------------------------------------------------
// Batched split: fp32 -> planar bf16 hi/lo for x + 6 weights in ONE launch.
// (x-lo is produced but no longer consumed; cost is negligible.)
// ---------------------------------------------------------------------------
struct SplitArgs {
    const float4* in[7];
    uint32_t* hi[7];
    uint32_t* lo[7];
    int start[8];
};
__global__ void split_all(SplitArgs a)
{
    int i = blockIdx.x * 256 + threadIdx.x;
    if (i >= a.start[7]) return;
    int seg = 0;
#pragma unroll
    for (int s = 1; s < 7; s++) if (i >= a.start[s]) seg = s;
    int loc = i - a.start[seg];
    float4 v = a.in[seg][loc];
    uint32_t h0, l0, h1, l1;
    split2(v.x, v.y, h0, l0);
    split2(v.z, v.w, h1, l1);
    a.hi[seg][loc * 2] = h0; a.hi[seg][loc * 2 + 1] = h1;
    a.lo[seg][loc * 2] = l0; a.lo[seg][loc * 2 + 1] = l1;
}

// ---------------------------------------------------------------------------
// HMMA GEMM body: 2-term (ah*bh + ah*bl), 4-stage cp.async pipeline,
// ONE __syncthreads per chunk, order: wait -> sync -> compute -> prefetch.
// CTA 128x128, BK=32, 8 warps 4x2, 2 CTAs/SM.
// Stage (27648 B): [AH 10240 | BH 8704 | BL 8704]
// OUT: 0 = fp32; 1 = bf16 (scaled)
// ---------------------------------------------------------------------------
#define STSZ   27648u
#define B_OFF  10240u
#define BL_REL 8704u
#define GEMM_SMEM (4 * 27648)

template<int OUT, bool RELU, bool RESID>
__device__ __forceinline__ void
gemm_body(const bf* __restrict__ Ahi,
          const bf* __restrict__ Bhi, const bf* __restrict__ Blo,
          const float* __restrict__ bias, const float* __restrict__ R,
          void* __restrict__ out0,
          int M, int N, int K, float scale, int m0, int n0, char* smem)
{
    const uint32_t sb = smem_u32(smem);
    const int tid  = threadIdx.x;
    const int wid  = tid >> 5;
    const int lane = tid & 31;

    const int m_base = (wid & 3) * 32;
    const int n_base = (wid >> 2) * 64;

    const int ar = tid >> 2, aseg = tid & 3;
    const int br = tid >> 4, bseg = tid & 15;

    auto copyStage = [&](uint32_t buf, int ic) {
        const int k0 = ic << 5;
        const uint32_t st = sb + buf * STSZ;
#pragma unroll
        for (int it = 0; it < 2; it++) {
            int r = ar + it * 64;
            bool ok = (m0 + r) < M;
            size_t off = (size_t)(m0 + r) * K + k0 + aseg * 8;
            cp16(st + (uint32_t)(r * 80 + aseg * 16), Ahi + off, ok);
        }
#pragma unroll
        for (int it = 0; it < 2; it++) {
            int r = br + it * 16;
            size_t off = (size_t)(k0 + r) * N + n0 + bseg * 8;
            uint32_t d = st + B_OFF + (uint32_t)(r * 272 + bseg * 16);
            cp16(d, Bhi + off, true);
            cp16(d + BL_REL, Blo + off, true);
        }
        cp_commit();
    };

    const uint32_t a_off = (uint32_t)((m_base + (lane & 15)) * 80 + (lane >> 4) * 16);
    const uint32_t b_off = B_OFF + (uint32_t)((lane & 15) * 272 + (n_base + (lane >> 4) * 8) * 2);

    float acc[2][8][4];
#pragma unroll
    for (int mf = 0; mf < 2; mf++)
#pragma unroll
        for (int nf = 0; nf < 8; nf++)
#pragma unroll
            for (int i = 0; i < 4; i++) acc[mf][nf][i] = 0.f;

    const int NC = K >> 5;     // >= 8 for all our shapes
    copyStage(0, 0);
    copyStage(1, 1);
    copyStage(2, 2);

    uint32_t buf = 0;
    for (int ic = 0; ic < NC; ic++) {
        cp_wait2();          // own groups: chunk ic copy complete (ic+1, ic+2 in flight)
        __syncthreads();     // publish all threads' chunk-ic copies; retire compute of ic-1

        const uint32_t st = sb + buf * STSZ;
#pragma unroll
        for (int ks = 0; ks < 2; ks++) {
            uint32_t ah[2][4], bb[8][2];
#pragma unroll
            for (int mf = 0; mf < 2; mf++)
                ldsm_x4(ah[mf], st + a_off + (uint32_t)(mf * 16 * 80 + ks * 32));
            // B-hi fragments
#pragma unroll
            for (int p = 0; p < 4; p++) {
                uint32_t t[4];
                ldsm_x4_t(t, st + b_off + (uint32_t)(ks * 16 * 272 + p * 32));
                bb[2 * p][0] = t[0]; bb[2 * p][1] = t[1];
                bb[2 * p + 1][0] = t[2]; bb[2 * p + 1][1] = t[3];
            }
#pragma unroll
            for (int nf = 0; nf < 8; nf++)
#pragma unroll
                for (int mf = 0; mf < 2; mf++)
                    mma_bf16(acc[mf][nf], ah[mf], bb[nf]);
            // B-lo fragments reuse bb registers
#pragma unroll
            for (int p = 0; p < 4; p++) {
                uint32_t t[4];
                ldsm_x4_t(t, st + b_off + (uint32_t)(ks * 16 * 272 + p * 32) + BL_REL);
                bb[2 * p][0] = t[0]; bb[2 * p][1] = t[1];
                bb[2 * p + 1][0] = t[2]; bb[2 * p + 1][1] = t[3];
            }
#pragma unroll
            for (int nf = 0; nf < 8; nf++)
#pragma unroll
                for (int mf = 0; mf < 2; mf++)
                    mma_bf16(acc[mf][nf], ah[mf], bb[nf]);
        }

        // prefetch chunk ic+3 into buffer (buf+3)%4 (= buffer of chunk ic-1,
        // retired by this iteration's barrier). Empty commit keeps the
        // one-group-per-iteration invariant for cp_wait2.
        if (ic + 3 < NC) copyStage((buf + 3) & 3, ic + 3);
        else cp_commit();

        buf = (buf + 1) & 3;
    }

    auto emit = [&](int row, int c, float v0, float v1) {
        size_t off = (size_t)row * N + c;
        v0 += bias[c]; v1 += bias[c + 1];
        if (RESID) { float2 rv = *(const float2*)(R + off); v0 += rv.x; v1 += rv.y; }
        if (RELU)  { v0 = fmaxf(v0, 0.f); v1 = fmaxf(v1, 0.f); }
        if (OUT == 0) {
            *(float2*)((float*)out0 + off) = make_float2(v0, v1);
        } else {
            v0 *= scale; v1 *= scale;
            __nv_bfloat162 h = __floats2bfloat162_rn(v0, v1);
            *(__nv_bfloat162*)((bf*)out0 + off) = h;
        }
    };
#pragma unroll
    for (int mf = 0; mf < 2; mf++) {
        const int r0 = m0 + m_base + mf * 16 + (lane >> 2);
#pragma unroll
        for (int nf = 0; nf < 8; nf++) {
            const int c = n0 + n_base + nf * 8 + (lane & 3) * 2;
            if (r0 < M)     emit(r0,     c, acc[mf][nf][0], acc[mf][nf][1]);
            if (r0 + 8 < M) emit(r0 + 8, c, acc[mf][nf][2], acc[mf][nf][3]);
        }
    }
}

template<int OUT, bool RELU, bool RESID>
__global__ void __launch_bounds__(256, 2)
gemm_bf(const bf* __restrict__ Ahi,
        const bf* __restrict__ Bhi, const bf* __restrict__ Blo,
        const float* __restrict__ bias, const float* __restrict__ R,
        void* __restrict__ out0,
        int M, int N, int K, float scale)
{
    extern __shared__ char smem[];
    gemm_body<OUT, RELU, RESID>(Ahi, Bhi, Blo, bias, R, out0,
                                M, N, K, scale, blockIdx.x * 128, blockIdx.y * 128, smem);
}

// Fused QKV: grid.y in [0,6); weight = y>>1, n-tile = y&1. 2-term (x-hi only).
struct QKVArgs {
    const bf* wh[3]; const bf* wl[3];
    const float* bias[3];
    bf* out[3];
    float scale[3];
};
__global__ void __launch_bounds__(256, 2)
gemm_qkv(const bf* __restrict__ Ahi, QKVArgs args, int M)
{
    extern __shared__ char smem[];
    const int sel = blockIdx.y >> 1;
    const int n0  = (blockIdx.y & 1) * 128;
    gemm_body<1, false, false>(Ahi, args.wh[sel], args.wl[sel],
                               args.bias[sel], nullptr, args.out[sel],
                               M, DMODEL, DMODEL, args.scale[sel],
                               blockIdx.x * 128, n0, smem);
}

// ---------------------------------------------------------------------------
// Tensor-core flash attention, no-max softmax, exp2-folded Q scale.
// Output: single bf16. (unchanged)
// ---------------------------------------------------------------------------
#define AT_K_OFF 28160
#define AT_V_OFF 55040
#define AT_SMEM  81920

__global__ void __launch_bounds__(352)
attn_mma(const bf* __restrict__ qg, const bf* __restrict__ kg,
         const bf* __restrict__ vg, bf* __restrict__ og)
{
    extern __shared__ char smem[];
    const uint32_t sb = smem_u32(smem);
    const int h  = blockIdx.x & (NHEAD - 1);
    const int bs = blockIdx.x >> 3;
    const int base = bs * NNODE;
    const int tid = threadIdx.x, lane = tid & 31, w = tid >> 5;

    for (int idx = tid; idx < 352 * 4; idx += 352) {
        int r = idx >> 2, seg = idx & 3;
        uint4 v = make_uint4(0, 0, 0, 0);
        if (r < NNODE)
            v = *(const uint4*)(qg + (size_t)(base + r) * DMODEL + h * HD + seg * 8);
        *(uint4*)(smem + r * 80 + seg * 16) = v;
    }
    for (int idx = tid; idx < NPAD * 4; idx += 352) {
        int r = idx >> 2, seg = idx & 3;
        uint4 kv = make_uint4(0, 0, 0, 0), vv = make_uint4(0, 0, 0, 0);
        if (r < NNODE) {
            kv = *(const uint4*)(kg + (size_t)(base + r) * DMODEL + h * HD + seg * 8);
            vv = *(const uint4*)(vg + (size_t)(base + r) * DMODEL + h * HD + seg * 8);
        }
        *(uint4*)(smem + AT_K_OFF + r * 80 + seg * 16) = kv;
        *(uint4*)(smem + AT_V_OFF + r * 80 + seg * 16) = vv;
    }
    __syncthreads();

    const int m_base = w * 32;
    uint32_t qf[2][2][4];
#pragma unroll
    for (int mf = 0; mf < 2; mf++)
#pragma unroll
        for (int kf = 0; kf < 2; kf++)
            ldsm_x4(qf[mf][kf],
                    sb + (uint32_t)((m_base + mf * 16 + (lane & 15)) * 80
                                    + kf * 32 + (lane >> 4) * 16));

    float o[2][4][4];
#pragma unroll
    for (int mf = 0; mf < 2; mf++)
#pragma unroll
        for (int nh = 0; nh < 4; nh++)
#pragma unroll
            for (int i = 0; i < 4; i++) o[mf][nh][i] = 0.f;
    float l[4] = {0.f, 0.f, 0.f, 0.f};

    for (int kt = 0; kt < NKT; kt++) {
        uint32_t kb[2][2][2];
#pragma unroll
        for (int kf = 0; kf < 2; kf++) {
            uint32_t t[4];
            ldsm_x4(t, sb + AT_K_OFF
                       + (uint32_t)((kt * 16 + (lane & 15)) * 80 + kf * 32 + (lane >> 4) * 16));
            kb[kf][0][0] = t[0]; kb[kf][0][1] = t[2];
            kb[kf][1][0] = t[1]; kb[kf][1][1] = t[3];
        }
        float s[2][2][4];
#pragma unroll
        for (int mf = 0; mf < 2; mf++)
#pragma unroll
            for (int nf = 0; nf < 2; nf++) {
#pragma unroll
                for (int i = 0; i < 4; i++) s[mf][nf][i] = 0.f;
#pragma unroll
                for (int kf = 0; kf < 2; kf++)
                    mma_bf16(s[mf][nf], qf[mf][kf], kb[kf][nf]);
            }
        if (kt == NKT - 1) {
#pragma unroll
            for (int nf = 0; nf < 2; nf++)
#pragma unroll
                for (int j = 0; j < 4; j++) {
                    int col = kt * 16 + nf * 8 + (lane & 3) * 2 + (j & 1);
                    if (col >= NNODE) { s[0][nf][j] = -1e30f; s[1][nf][j] = -1e30f; }
                }
        }
        uint32_t pa[2][4];
#pragma unroll
        for (int mf = 0; mf < 2; mf++) {
#pragma unroll
            for (int half = 0; half < 2; half++) {
                const int slot = mf * 2 + half;
                float p0 = exp2f(s[mf][0][half * 2]);
                float p1 = exp2f(s[mf][0][half * 2 + 1]);
                float p2 = exp2f(s[mf][1][half * 2]);
                float p3 = exp2f(s[mf][1][half * 2 + 1]);
                l[slot] += (p0 + p1) + (p2 + p3);
                s[mf][0][half * 2] = p0; s[mf][0][half * 2 + 1] = p1;
                s[mf][1][half * 2] = p2; s[mf][1][half * 2 + 1] = p3;
            }
            __nv_bfloat162 t;
            t = __floats2bfloat162_rn(s[mf][0][0], s[mf][0][1]); pa[mf][0] = *(uint32_t*)&t;
            t = __floats2bfloat162_rn(s[mf][0][2], s[mf][0][3]); pa[mf][1] = *(uint32_t*)&t;
            t = __floats2bfloat162_rn(s[mf][1][0], s[mf][1][1]); pa[mf][2] = *(uint32_t*)&t;
            t = __floats2bfloat162_rn(s[mf][1][2], s[mf][1][3]); pa[mf][3] = *(uint32_t*)&t;
        }
        uint32_t vf[4][2];
#pragma unroll
        for (int vh = 0; vh < 2; vh++) {
            uint32_t t[4];
            ldsm_x4_t(t, sb + AT_V_OFF
                         + (uint32_t)((kt * 16 + (lane & 15)) * 80 + vh * 32 + (lane >> 4) * 16));
            vf[2 * vh][0] = t[0]; vf[2 * vh][1] = t[1];
            vf[2 * vh + 1][0] = t[2]; vf[2 * vh + 1][1] = t[3];
        }
#pragma unroll
        for (int mf = 0; mf < 2; mf++)
#pragma unroll
            for (int nh = 0; nh < 4; nh++)
                mma_bf16(o[mf][nh], pa[mf], vf[nh]);
    }

#pragma unroll
    for (int slot = 0; slot < 4; slot++) {
        l[slot] += __shfl_xor_sync(0xffffffffu, l[slot], 1);
        l[slot] += __shfl_xor_sync(0xffffffffu, l[slot], 2);
        l[slot] = 1.f / l[slot];
    }
#pragma unroll
    for (int mf = 0; mf < 2; mf++)
#pragma unroll
        for (int half = 0; half < 2; half++) {
            const int slot = mf * 2 + half;
            const int r = m_base + mf * 16 + half * 8 + (lane >> 2);
            if (r >= NNODE) continue;
            const size_t rowoff = (size_t)(base + r) * DMODEL + h * HD;
#pragma unroll
            for (int nh = 0; nh < 4; nh++) {
                const int c = nh * 8 + (lane & 3) * 2;
                float v0 = o[mf][nh][half * 2] * l[slot];
                float v1 = o[mf][nh][half * 2 + 1] * l[slot];
                __nv_bfloat162 hh = __floats2bfloat162_rn(v0, v1);
                *(__nv_bfloat162*)(og + rowoff + c) = hh;
            }
        }
}

// ---------------------------------------------------------------------------
// LayerNorm; optionally also emit bf16 (hi-only) plane of the output.
// ---------------------------------------------------------------------------
template<bool PLANES>
__global__ void __launch_bounds__(256)
ln_k(const float* __restrict__ in, const float* __restrict__ g,
     const float* __restrict__ bt, float* __restrict__ out,
     bf* __restrict__ phi)
{
    const int lane = threadIdx.x & 31;
    const int w    = threadIdx.x >> 5;
    const size_t row = (size_t)blockIdx.x * 8 + w;

    const float4* r = (const float4*)(in + row * DMODEL);
    float4 a = r[lane * 2], b = r[lane * 2 + 1];
    float s = a.x + a.y + a.z + a.w + b.x + b.y + b.z + b.w;
    float qs = a.x * a.x + a.y * a.y + a.z * a.z + a.w * a.w +
               b.x * b.x + b.y * b.y + b.z * b.z + b.w * b.w;
#pragma unroll
    for (int off = 16; off; off >>= 1) {
        s  += __shfl_xor_sync(0xffffffffu, s,  off);
        qs += __shfl_xor_sync(0xffffffffu, qs, off);
    }
    const float mean = s * (1.f / DMODEL);
    const float var  = qs * (1.f / DMODEL) - mean * mean;
    const float rstd = rsqrtf(var + 1e-5f);

    const float4* gv = (const float4*)g;
    const float4* bv = (const float4*)bt;
    float4 g0 = gv[lane * 2], g1 = gv[lane * 2 + 1];
    float4 b0 = bv[lane * 2], b1 = bv[lane * 2 + 1];

    float4 o0, o1;
    o0.x = (a.x - mean) * rstd * g0.x + b0.x;
    o0.y = (a.y - mean) * rstd * g0.y + b0.y;
    o0.z = (a.z - mean) * rstd * g0.z + b0.z;
    o0.w = (a.w - mean) * rstd * g0.w + b0.w;
    o1.x = (b.x - mean) * rstd * g1.x + b1.x;
    o1.y = (b.y - mean) * rstd * g1.y + b1.y;
    o1.z = (b.z - mean) * rstd * g1.z + b1.z;
    o1.w = (b.w - mean) * rstd * g1.w + b1.w;

    float4* op = (float4*)(out + row * DMODEL);
    op[lane * 2]     = o0;
    op[lane * 2 + 1] = o1;

    if (PLANES) {
        __nv_bfloat162 h0 = __floats2bfloat162_rn(o0.x, o0.y);
        __nv_bfloat162 h1 = __floats2bfloat162_rn(o0.z, o0.w);
        __nv_bfloat162 h2 = __floats2bfloat162_rn(o1.x, o1.y);
        __nv_bfloat162 h3 = __floats2bfloat162_rn(o1.z, o1.w);
        uint4* ph = (uint4*)(phi + row * DMODEL);
        ph[lane] = make_uint4(*(uint32_t*)&h0, *(uint32_t*)&h1,
                              *(uint32_t*)&h2, *(uint32_t*)&h3);
    }
}

// ---------------------------------------------------------------------------
// Launch
// ---------------------------------------------------------------------------
extern "C" void kernel_launch(void* const* d_in, const int* in_sizes, int n_in,
                              void* d_out, int out_size)
{
    const float* x   = (const float*)d_in[0];
    const float* Wq  = (const float*)d_in[1];
    const float* bq  = (const float*)d_in[2];
    const float* Wk  = (const float*)d_in[3];
    const float* bk  = (const float*)d_in[4];
    const float* Wv  = (const float*)d_in[5];
    const float* bv  = (const float*)d_in[6];
    const float* Wo  = (const float*)d_in[7];
    const float* bo  = (const float*)d_in[8];
    const float* W1  = (const float*)d_in[9];
    const float* b1  = (const float*)d_in[10];
    const float* W2  = (const float*)d_in[11];
    const float* b2  = (const float*)d_in[12];
    const float* g1  = (const float*)d_in[13];
    const float* be1 = (const float*)d_in[14];
    const float* g2  = (const float*)d_in[15];
    const float* be2 = (const float*)d_in[16];
    float* out = (float*)d_out;

    float* base = nullptr;
    cudaGetSymbolAddress((void**)&base, g_scratch);
    const size_t T = TSLICE;

    bf* xh  = (bf*)base;            bf* xl  = xh + T;          // [0, T)
    bf* qb  = (bf*)(base + T);                                  // [T, 1.5T)
    bf* kb  = (bf*)(base + T + T / 2);                          // [1.5T, 2T)
    bf* vb  = (bf*)(base + 2 * T);                              // [2T, 2.5T)
    bf* ath = (bf*)(base + 2 * T + T / 2);                      // [2.5T, 3T)
    float* res = base + 3 * T + T / 2;                          // [3.5T, 4.5T)
    float* ln1 = base + 4 * T + T / 2;                          // [4.5T, 5.5T)
    bf* l1h = (bf*)(base + 5 * T + T / 2);                      // [5.5T, 6T)
    bf* fh  = (bf*)(base + 6 * T + T / 2);                      // [6.5T, 6.5T+FSLICE/2)
    float* wc = base + 6 * T + T / 2 + FSLICE;
    bf* wqh = (bf*)wc;            bf* wql = wqh + 65536;  wc += 65536;
    bf* wkh = (bf*)wc;            bf* wkl = wkh + 65536;  wc += 65536;
    bf* wvh = (bf*)wc;            bf* wvl = wvh + 65536;  wc += 65536;
    bf* woh = (bf*)wc;            bf* wol = woh + 65536;  wc += 65536;
    bf* w1h = (bf*)wc;            bf* w1l = w1h + 524288; wc += 524288;
    bf* w2h = (bf*)wc;            bf* w2l = w2h + 524288; wc += 524288;

    const int M = MTOK;
    const int mt = (M + 127) / 128;

    // batched operand splits (x + 6 weight matrices) in one launch
    SplitArgs sa;
    sa.in[0] = (const float4*)x;  sa.hi[0] = (uint32_t*)xh;  sa.lo[0] = (uint32_t*)xl;
    sa.in[1] = (const float4*)Wq; sa.hi[1] = (uint32_t*)wqh; sa.lo[1] = (uint32_t*)wql;
    sa.in[2] = (const float4*)Wk; sa.hi[2] = (uint32_t*)wkh; sa.lo[2] = (uint32_t*)wkl;
    sa.in[3] = (const float4*)Wv; sa.hi[3] = (uint32_t*)wvh; sa.lo[3] = (uint32_t*)wvl;
    sa.in[4] = (const float4*)Wo; sa.hi[4] = (uint32_t*)woh; sa.lo[4] = (uint32_t*)wol;
    sa.in[5] = (const float4*)W1; sa.hi[5] = (uint32_t*)w1h; sa.lo[5] = (uint32_t*)w1l;
    sa.in[6] = (const float4*)W2; sa.hi[6] = (uint32_t*)w2h; sa.lo[6] = (uint32_t*)w2l;
    int xs = (int)(T / 4);
    sa.start[0] = 0;
    sa.start[1] = xs;
    sa.start[2] = xs + 16384;
    sa.start[3] = xs + 32768;
    sa.start[4] = xs + 49152;
    sa.start[5] = xs + 65536;
    sa.start[6] = xs + 65536 + 131072;
    sa.start[7] = xs + 65536 + 262144;
    split_all<<<(sa.start[7] + 255) / 256, 256>>>(sa);

    cudaFuncSetAttribute(gemm_qkv, cudaFuncAttributeMaxDynamicSharedMemorySize, GEMM_SMEM);
    cudaFuncSetAttribute(gemm_bf<0, false, true >, cudaFuncAttributeMaxDynamicSharedMemorySize, GEMM_SMEM);
    cudaFuncSetAttribute(gemm_bf<1, true,  false>, cudaFuncAttributeMaxDynamicSharedMemorySize, GEMM_SMEM);
    cudaFuncSetAttribute(attn_mma, cudaFuncAttributeMaxDynamicSharedMemorySize, AT_SMEM);

    // q scale: 1/sqrt(32) * log2(e)  (softmax uses exp2)
    const float qscale = 0.17677669529663687f * 1.4426950408889634f;

    // fused QKV (2-term: x-hi only) -> bf16 (q scaled)
    QKVArgs qa;
    qa.wh[0] = wqh; qa.wh[1] = wkh; qa.wh[2] = wvh;
    qa.wl[0] = wql; qa.wl[1] = wkl; qa.wl[2] = wvl;
    qa.bias[0] = bq; qa.bias[1] = bk; qa.bias[2] = bv;
    qa.out[0] = qb; qa.out[1] = kb; qa.out[2] = vb;
    qa.scale[0] = qscale; qa.scale[1] = 1.f; qa.scale[2] = 1.f;
    gemm_qkv<<<dim3(mt, 6), 256, GEMM_SMEM>>>(xh, qa, M);

    // attention -> single bf16
    attn_mma<<<16 * 12 * NHEAD, 352, AT_SMEM>>>(qb, kb, vb, ath);

    // O-proj (2-term) + residual(x) -> res fp32; LN1 -> ln1 + hi plane
    gemm_bf<0, false, true><<<dim3(mt, 2), 256, GEMM_SMEM>>>(ath, woh, wol, bo, x, res, M, DMODEL, DMODEL, 1.f);
    ln_k<true><<<M / 8, 256>>>(res, g1, be1, ln1, l1h);

    // FFN1 (2-term) -> single bf16 (relu); FFN2 (2-term) + residual(ln1) -> res; LN2 -> out
    gemm_bf<1, true,  false><<<dim3(mt, 16), 256, GEMM_SMEM>>>(l1h, w1h, w1l, b1, nullptr, fh, M, FDIM, DMODEL, 1.f);
    gemm_bf<0, false, true ><<<dim3(mt, 2), 256, GEMM_SMEM>>>(fh, w2h, w2l, b2, ln1, res, M, DMODEL, FDIM, 1.f);
    ln_k<false><<<M / 8, 256>>>(res, g2, be2, out, nullptr);

    (void)in_sizes; (void)n_in; (void)out_size;
}

// round 14
// speedup vs baseline: 1.0196x; 1.0196x over previous
#include <cuda_runtime.h>
#include <cuda_bf16.h>
#include <cstdint>

// Problem constants
#define MTOK   62400      // B*S*N
#define DMODEL 256
#define FDIM   2048
#define NHEAD  8
#define HD     32
#define NNODE  325
#define NPAD   336        // 21 * 16
#define NKT    21

#define TSLICE ((size_t)MTOK * DMODEL)     // 15,974,400
#define FSLICE ((size_t)MTOK * FDIM)       // 127,795,200
__device__ float g_scratch[7 * TSLICE + FSLICE];

typedef __nv_bfloat16 bf;

// ---------------------------------------------------------------------------
// PTX helpers
// ---------------------------------------------------------------------------
__device__ __forceinline__ uint32_t smem_u32(const void* p) {
    uint32_t a;
    asm("{ .reg .u64 t; cvta.to.shared.u64 t, %1; cvt.u32.u64 %0, t; }" : "=r"(a) : "l"(p));
    return a;
}
__device__ __forceinline__ void ldsm_x4(uint32_t* r, uint32_t addr) {
    asm volatile("ldmatrix.sync.aligned.m8n8.x4.shared.b16 {%0,%1,%2,%3}, [%4];"
                 : "=r"(r[0]), "=r"(r[1]), "=r"(r[2]), "=r"(r[3]) : "r"(addr));
}
__device__ __forceinline__ void ldsm_x4_t(uint32_t* r, uint32_t addr) {
    asm volatile("ldmatrix.sync.aligned.m8n8.x4.trans.shared.b16 {%0,%1,%2,%3}, [%4];"
                 : "=r"(r[0]), "=r"(r[1]), "=r"(r[2]), "=r"(r[3]) : "r"(addr));
}
__device__ __forceinline__ void mma_bf16(float* d, const uint32_t* a, const uint32_t* b) {
    asm volatile("mma.sync.aligned.m16n8k16.row.col.f32.bf16.bf16.f32 "
                 "{%0,%1,%2,%3}, {%4,%5,%6,%7}, {%8,%9}, {%0,%1,%2,%3};"
                 : "+f"(d[0]), "+f"(d[1]), "+f"(d[2]), "+f"(d[3])
                 : "r"(a[0]), "r"(a[1]), "r"(a[2]), "r"(a[3]), "r"(b[0]), "r"(b[1]));
}
__device__ __forceinline__ void cp16(uint32_t dst, const void* src, bool pred) {
    int sz = pred ? 16 : 0;
    asm volatile("cp.async.cg.shared.global [%0], [%1], 16, %2;"
                 :: "r"(dst), "l"(src), "r"(sz));
}
__device__ __forceinline__ void cp_commit() {
    asm volatile("cp.async.commit_group;" ::: "memory");
}
__device__ __forceinline__ void cp_wait1() {
    asm volatile("cp.async.wait_group 1;" ::: "memory");
}
__device__ __forceinline__ void split2(float x, float y, uint32_t& hi, uint32_t& lo) {
    __nv_bfloat162 h = __floats2bfloat162_rn(x, y);
    float2 hf = __bfloat1622float2(h);
    __nv_bfloat162 l = __floats2bfloat162_rn(x - hf.x, y - hf.y);
    hi = *reinterpret_cast<uint32_t*>(&h);
    lo = *reinterpret_cast<uint32_t*>(&l);
}

// ---------------------------------------------------------------------------
// Batched split: fp32 -> planar bf16 hi/lo for x + 6 weights in ONE launch.
// ---------------------------------------------------------------------------
struct SplitArgs {
    const float4* in[7];
    uint32_t* hi[7];
    uint32_t* lo[7];
    int start[8];
};
__global__ void split_all(SplitArgs a)
{
    int i = blockIdx.x * 256 + threadIdx.x;
    if (i >= a.start[7]) return;
    int seg = 0;
#pragma unroll
    for (int s = 1; s < 7; s++) if (i >= a.start[s]) seg = s;
    int loc = i - a.start[seg];
    float4 v = a.in[seg][loc];
    uint32_t h0, l0, h1, l1;
    split2(v.x, v.y, h0, l0);
    split2(v.z, v.w, h1, l1);
    a.hi[seg][loc * 2] = h0; a.hi[seg][loc * 2 + 1] = h1;
    a.lo[seg][loc * 2] = l0; a.lo[seg][loc * 2 + 1] = l1;
}

// ---------------------------------------------------------------------------
// HMMA GEMM body: 2-term (ah*bh + ah*bl), 3-stage cp.async pipeline,
// ONE __syncthreads per chunk, order: wait -> sync -> compute -> prefetch.
// CTA 128x128, BK=32, 8 warps 4x2, 2 CTAs/SM (smem 82944/CTA keeps L1D alive).
// Stage (27648 B): [AH 10240 | BH 8704 | BL 8704]
// OUT: 0 = fp32; 1 = bf16 (scaled)
// ---------------------------------------------------------------------------
#define STSZ   27648u
#define B_OFF  10240u
#define BL_REL 8704u
#define GEMM_SMEM (3 * 27648)

template<int OUT, bool RELU, bool RESID>
__device__ __forceinline__ void
gemm_body(const bf* __restrict__ Ahi,
          const bf* __restrict__ Bhi, const bf* __restrict__ Blo,
          const float* __restrict__ bias, const float* __restrict__ R,
          void* __restrict__ out0,
          int M, int N, int K, float scale, int m0, int n0, char* smem)
{
    const uint32_t sb = smem_u32(smem);
    const int tid  = threadIdx.x;
    const int wid  = tid >> 5;
    const int lane = tid & 31;

    const int m_base = (wid & 3) * 32;
    const int n_base = (wid >> 2) * 64;

    const int ar = tid >> 2, aseg = tid & 3;
    const int br = tid >> 4, bseg = tid & 15;

    auto copyStage = [&](uint32_t buf, int ic) {
        const int k0 = ic << 5;
        const uint32_t st = sb + buf * STSZ;
#pragma unroll
        for (int it = 0; it < 2; it++) {
            int r = ar + it * 64;
            bool ok = (m0 + r) < M;
            size_t off = (size_t)(m0 + r) * K + k0 + aseg * 8;
            cp16(st + (uint32_t)(r * 80 + aseg * 16), Ahi + off, ok);
        }
#pragma unroll
        for (int it = 0; it < 2; it++) {
            int r = br + it * 16;
            size_t off = (size_t)(k0 + r) * N + n0 + bseg * 8;
            uint32_t d = st + B_OFF + (uint32_t)(r * 272 + bseg * 16);
            cp16(d, Bhi + off, true);
            cp16(d + BL_REL, Blo + off, true);
        }
        cp_commit();
    };

    const uint32_t a_off = (uint32_t)((m_base + (lane & 15)) * 80 + (lane >> 4) * 16);
    const uint32_t b_off = B_OFF + (uint32_t)((lane & 15) * 272 + (n_base + (lane >> 4) * 8) * 2);

    float acc[2][8][4];
#pragma unroll
    for (int mf = 0; mf < 2; mf++)
#pragma unroll
        for (int nf = 0; nf < 8; nf++)
#pragma unroll
            for (int i = 0; i < 4; i++) acc[mf][nf][i] = 0.f;

    const int NC = K >> 5;     // >= 8 for all our shapes
    copyStage(0, 0);
    copyStage(1, 1);

    uint32_t buf = 0;
    for (int ic = 0; ic < NC; ic++) {
        cp_wait1();          // own groups: chunk ic copy complete (ic+1 in flight)
        __syncthreads();     // publish all threads' chunk-ic copies; retire compute of ic-1

        const uint32_t st = sb + buf * STSZ;
#pragma unroll
        for (int ks = 0; ks < 2; ks++) {
            uint32_t ah[2][4], bb[8][2];
#pragma unroll
            for (int mf = 0; mf < 2; mf++)
                ldsm_x4(ah[mf], st + a_off + (uint32_t)(mf * 16 * 80 + ks * 32));
            // B-hi fragments
#pragma unroll
            for (int p = 0; p < 4; p++) {
                uint32_t t[4];
                ldsm_x4_t(t, st + b_off + (uint32_t)(ks * 16 * 272 + p * 32));
                bb[2 * p][0] = t[0]; bb[2 * p][1] = t[1];
                bb[2 * p + 1][0] = t[2]; bb[2 * p + 1][1] = t[3];
            }
#pragma unroll
            for (int nf = 0; nf < 8; nf++)
#pragma unroll
                for (int mf = 0; mf < 2; mf++)
                    mma_bf16(acc[mf][nf], ah[mf], bb[nf]);
            // B-lo fragments reuse bb registers
#pragma unroll
            for (int p = 0; p < 4; p++) {
                uint32_t t[4];
                ldsm_x4_t(t, st + b_off + (uint32_t)(ks * 16 * 272 + p * 32) + BL_REL);
                bb[2 * p][0] = t[0]; bb[2 * p][1] = t[1];
                bb[2 * p + 1][0] = t[2]; bb[2 * p + 1][1] = t[3];
            }
#pragma unroll
            for (int nf = 0; nf < 8; nf++)
#pragma unroll
                for (int mf = 0; mf < 2; mf++)
                    mma_bf16(acc[mf][nf], ah[mf], bb[nf]);
        }

        // prefetch chunk ic+2 into buffer (buf+2)%3 (= buffer of chunk ic-1,
        // retired by this iteration's barrier). Empty commit keeps the
        // one-group-per-iteration invariant for cp_wait1.
        if (ic + 2 < NC) copyStage((buf + 2 >= 3) ? buf - 1 : buf + 2, ic + 2);
        else cp_commit();

        buf = (buf == 2) ? 0 : buf + 1;
    }

    auto emit = [&](int row, int c, float v0, float v1) {
        size_t off = (size_t)row * N + c;
        v0 += bias[c]; v1 += bias[c + 1];
        if (RESID) { float2 rv = *(const float2*)(R + off); v0 += rv.x; v1 += rv.y; }
        if (RELU)  { v0 = fmaxf(v0, 0.f); v1 = fmaxf(v1, 0.f); }
        if (OUT == 0) {
            *(float2*)((float*)out0 + off) = make_float2(v0, v1);
        } else {
            v0 *= scale; v1 *= scale;
            __nv_bfloat162 h = __floats2bfloat162_rn(v0, v1);
            *(__nv_bfloat162*)((bf*)out0 + off) = h;
        }
    };
#pragma unroll
    for (int mf = 0; mf < 2; mf++) {
        const int r0 = m0 + m_base + mf * 16 + (lane >> 2);
#pragma unroll
        for (int nf = 0; nf < 8; nf++) {
            const int c = n0 + n_base + nf * 8 + (lane & 3) * 2;
            if (r0 < M)     emit(r0,     c, acc[mf][nf][0], acc[mf][nf][1]);
            if (r0 + 8 < M) emit(r0 + 8, c, acc[mf][nf][2], acc[mf][nf][3]);
        }
    }
}

template<int OUT, bool RELU, bool RESID>
__global__ void __launch_bounds__(256, 2)
gemm_bf(const bf* __restrict__ Ahi,
        const bf* __restrict__ Bhi, const bf* __restrict__ Blo,
        const float* __restrict__ bias, const float* __restrict__ R,
        void* __restrict__ out0,
        int M, int N, int K, float scale)
{
    extern __shared__ char smem[];
    gemm_body<OUT, RELU, RESID>(Ahi, Bhi, Blo, bias, R, out0,
                                M, N, K, scale, blockIdx.x * 128, blockIdx.y * 128, smem);
}

// Fused QKV: grid.y in [0,6); weight = y>>1, n-tile = y&1. 2-term (x-hi only).
struct QKVArgs {
    const bf* wh[3]; const bf* wl[3];
    const float* bias[3];
    bf* out[3];
    float scale[3];
};
__global__ void __launch_bounds__(256, 2)
gemm_qkv(const bf* __restrict__ Ahi, QKVArgs args, int M)
{
    extern __shared__ char smem[];
    const int sel = blockIdx.y >> 1;
    const int n0  = (blockIdx.y & 1) * 128;
    gemm_body<1, false, false>(Ahi, args.wh[sel], args.wl[sel],
                               args.bias[sel], nullptr, args.out[sel],
                               M, DMODEL, DMODEL, args.scale[sel],
                               blockIdx.x * 128, n0, smem);
}

// ---------------------------------------------------------------------------
// Tensor-core flash attention, no-max softmax, exp2-folded Q scale.
// Output: single bf16. (unchanged)
// ---------------------------------------------------------------------------
#define AT_K_OFF 28160
#define AT_V_OFF 55040
#define AT_SMEM  81920

__global__ void __launch_bounds__(352)
attn_mma(const bf* __restrict__ qg, const bf* __restrict__ kg,
         const bf* __restrict__ vg, bf* __restrict__ og)
{
    extern __shared__ char smem[];
    const uint32_t sb = smem_u32(smem);
    const int h  = blockIdx.x & (NHEAD - 1);
    const int bs = blockIdx.x >> 3;
    const int base = bs * NNODE;
    const int tid = threadIdx.x, lane = tid & 31, w = tid >> 5;

    for (int idx = tid; idx < 352 * 4; idx += 352) {
        int r = idx >> 2, seg = idx & 3;
        uint4 v = make_uint4(0, 0, 0, 0);
        if (r < NNODE)
            v = *(const uint4*)(qg + (size_t)(base + r) * DMODEL + h * HD + seg * 8);
        *(uint4*)(smem + r * 80 + seg * 16) = v;
    }
    for (int idx = tid; idx < NPAD * 4; idx += 352) {
        int r = idx >> 2, seg = idx & 3;
        uint4 kv = make_uint4(0, 0, 0, 0), vv = make_uint4(0, 0, 0, 0);
        if (r < NNODE) {
            kv = *(const uint4*)(kg + (size_t)(base + r) * DMODEL + h * HD + seg * 8);
            vv = *(const uint4*)(vg + (size_t)(base + r) * DMODEL + h * HD + seg * 8);
        }
        *(uint4*)(smem + AT_K_OFF + r * 80 + seg * 16) = kv;
        *(uint4*)(smem + AT_V_OFF + r * 80 + seg * 16) = vv;
    }
    __syncthreads();

    const int m_base = w * 32;
    uint32_t qf[2][2][4];
#pragma unroll
    for (int mf = 0; mf < 2; mf++)
#pragma unroll
        for (int kf = 0; kf < 2; kf++)
            ldsm_x4(qf[mf][kf],
                    sb + (uint32_t)((m_base + mf * 16 + (lane & 15)) * 80
                                    + kf * 32 + (lane >> 4) * 16));

    float o[2][4][4];
#pragma unroll
    for (int mf = 0; mf < 2; mf++)
#pragma unroll
        for (int nh = 0; nh < 4; nh++)
#pragma unroll
            for (int i = 0; i < 4; i++) o[mf][nh][i] = 0.f;
    float l[4] = {0.f, 0.f, 0.f, 0.f};

    for (int kt = 0; kt < NKT; kt++) {
        uint32_t kb[2][2][2];
#pragma unroll
        for (int kf = 0; kf < 2; kf++) {
            uint32_t t[4];
            ldsm_x4(t, sb + AT_K_OFF
                       + (uint32_t)((kt * 16 + (lane & 15)) * 80 + kf * 32 + (lane >> 4) * 16));
            kb[kf][0][0] = t[0]; kb[kf][0][1] = t[2];
            kb[kf][1][0] = t[1]; kb[kf][1][1] = t[3];
        }
        float s[2][2][4];
#pragma unroll
        for (int mf = 0; mf < 2; mf++)
#pragma unroll
            for (int nf = 0; nf < 2; nf++) {
#pragma unroll
                for (int i = 0; i < 4; i++) s[mf][nf][i] = 0.f;
#pragma unroll
                for (int kf = 0; kf < 2; kf++)
                    mma_bf16(s[mf][nf], qf[mf][kf], kb[kf][nf]);
            }
        if (kt == NKT - 1) {
#pragma unroll
            for (int nf = 0; nf < 2; nf++)
#pragma unroll
                for (int j = 0; j < 4; j++) {
                    int col = kt * 16 + nf * 8 + (lane & 3) * 2 + (j & 1);
                    if (col >= NNODE) { s[0][nf][j] = -1e30f; s[1][nf][j] = -1e30f; }
                }
        }
        uint32_t pa[2][4];
#pragma unroll
        for (int mf = 0; mf < 2; mf++) {
#pragma unroll
            for (int half = 0; half < 2; half++) {
                const int slot = mf * 2 + half;
                float p0 = exp2f(s[mf][0][half * 2]);
                float p1 = exp2f(s[mf][0][half * 2 + 1]);
                float p2 = exp2f(s[mf][1][half * 2]);
                float p3 = exp2f(s[mf][1][half * 2 + 1]);
                l[slot] += (p0 + p1) + (p2 + p3);
                s[mf][0][half * 2] = p0; s[mf][0][half * 2 + 1] = p1;
                s[mf][1][half * 2] = p2; s[mf][1][half * 2 + 1] = p3;
            }
            __nv_bfloat162 t;
            t = __floats2bfloat162_rn(s[mf][0][0], s[mf][0][1]); pa[mf][0] = *(uint32_t*)&t;
            t = __floats2bfloat162_rn(s[mf][0][2], s[mf][0][3]); pa[mf][1] = *(uint32_t*)&t;
            t = __floats2bfloat162_rn(s[mf][1][0], s[mf][1][1]); pa[mf][2] = *(uint32_t*)&t;
            t = __floats2bfloat162_rn(s[mf][1][2], s[mf][1][3]); pa[mf][3] = *(uint32_t*)&t;
        }
        uint32_t vf[4][2];
#pragma unroll
        for (int vh = 0; vh < 2; vh++) {
            uint32_t t[4];
            ldsm_x4_t(t, sb + AT_V_OFF
                         + (uint32_t)((kt * 16 + (lane & 15)) * 80 + vh * 32 + (lane >> 4) * 16));
            vf[2 * vh][0] = t[0]; vf[2 * vh][1] = t[1];
            vf[2 * vh + 1][0] = t[2]; vf[2 * vh + 1][1] = t[3];
        }
#pragma unroll
        for (int mf = 0; mf < 2; mf++)
#pragma unroll
            for (int nh = 0; nh < 4; nh++)
                mma_bf16(o[mf][nh], pa[mf], vf[nh]);
    }

#pragma unroll
    for (int slot = 0; slot < 4; slot++) {
        l[slot] += __shfl_xor_sync(0xffffffffu, l[slot], 1);
        l[slot] += __shfl_xor_sync(0xffffffffu, l[slot], 2);
        l[slot] = 1.f / l[slot];
    }
#pragma unroll
    for (int mf = 0; mf < 2; mf++)
#pragma unroll
        for (int half = 0; half < 2; half++) {
            const int slot = mf * 2 + half;
            const int r = m_base + mf * 16 + half * 8 + (lane >> 2);
            if (r >= NNODE) continue;
            const size_t rowoff = (size_t)(base + r) * DMODEL + h * HD;
#pragma unroll
            for (int nh = 0; nh < 4; nh++) {
                const int c = nh * 8 + (lane & 3) * 2;
                float v0 = o[mf][nh][half * 2] * l[slot];
                float v1 = o[mf][nh][half * 2 + 1] * l[slot];
                __nv_bfloat162 hh = __floats2bfloat162_rn(v0, v1);
                *(__nv_bfloat162*)(og + rowoff + c) = hh;
            }
        }
}

// ---------------------------------------------------------------------------
// LayerNorm; optionally also emit bf16 (hi-only) plane of the output.
// ---------------------------------------------------------------------------
template<bool PLANES>
__global__ void __launch_bounds__(256)
ln_k(const float* __restrict__ in, const float* __restrict__ g,
     const float* __restrict__ bt, float* __restrict__ out,
     bf* __restrict__ phi)
{
    const int lane = threadIdx.x & 31;
    const int w    = threadIdx.x >> 5;
    const size_t row = (size_t)blockIdx.x * 8 + w;

    const float4* r = (const float4*)(in + row * DMODEL);
    float4 a = r[lane * 2], b = r[lane * 2 + 1];
    float s = a.x + a.y + a.z + a.w + b.x + b.y + b.z + b.w;
    float qs = a.x * a.x + a.y * a.y + a.z * a.z + a.w * a.w +
               b.x * b.x + b.y * b.y + b.z * b.z + b.w * b.w;
#pragma unroll
    for (int off = 16; off; off >>= 1) {
        s  += __shfl_xor_sync(0xffffffffu, s,  off);
        qs += __shfl_xor_sync(0xffffffffu, qs, off);
    }
    const float mean = s * (1.f / DMODEL);
    const float var  = qs * (1.f / DMODEL) - mean * mean;
    const float rstd = rsqrtf(var + 1e-5f);

    const float4* gv = (const float4*)g;
    const float4* bv = (const float4*)bt;
    float4 g0 = gv[lane * 2], g1 = gv[lane * 2 + 1];
    float4 b0 = bv[lane * 2], b1 = bv[lane * 2 + 1];

    float4 o0, o1;
    o0.x = (a.x - mean) * rstd * g0.x + b0.x;
    o0.y = (a.y - mean) * rstd * g0.y + b0.y;
    o0.z = (a.z - mean) * rstd * g0.z + b0.z;
    o0.w = (a.w - mean) * rstd * g0.w + b0.w;
    o1.x = (b.x - mean) * rstd * g1.x + b1.x;
    o1.y = (b.y - mean) * rstd * g1.y + b1.y;
    o1.z = (b.z - mean) * rstd * g1.z + b1.z;
    o1.w = (b.w - mean) * rstd * g1.w + b1.w;

    float4* op = (float4*)(out + row * DMODEL);
    op[lane * 2]     = o0;
    op[lane * 2 + 1] = o1;

    if (PLANES) {
        __nv_bfloat162 h0 = __floats2bfloat162_rn(o0.x, o0.y);
        __nv_bfloat162 h1 = __floats2bfloat162_rn(o0.z, o0.w);
        __nv_bfloat162 h2 = __floats2bfloat162_rn(o1.x, o1.y);
        __nv_bfloat162 h3 = __floats2bfloat162_rn(o1.z, o1.w);
        uint4* ph = (uint4*)(phi + row * DMODEL);
        ph[lane] = make_uint4(*(uint32_t*)&h0, *(uint32_t*)&h1,
                              *(uint32_t*)&h2, *(uint32_t*)&h3);
    }
}

// ---------------------------------------------------------------------------
// Launch
// ---------------------------------------------------------------------------
extern "C" void kernel_launch(void* const* d_in, const int* in_sizes, int n_in,
                              void* d_out, int out_size)
{
    const float* x   = (const float*)d_in[0];
    const float* Wq  = (const float*)d_in[1];
    const float* bq  = (const float*)d_in[2];
    const float* Wk  = (const float*)d_in[3];
    const float* bk  = (const float*)d_in[4];
    const float* Wv  = (const float*)d_in[5];
    const float* bv  = (const float*)d_in[6];
    const float* Wo  = (const float*)d_in[7];
    const float* bo  = (const float*)d_in[8];
    const float* W1  = (const float*)d_in[9];
    const float* b1  = (const float*)d_in[10];
    const float* W2  = (const float*)d_in[11];
    const float* b2  = (const float*)d_in[12];
    const float* g1  = (const float*)d_in[13];
    const float* be1 = (const float*)d_in[14];
    const float* g2  = (const float*)d_in[15];
    const float* be2 = (const float*)d_in[16];
    float* out = (float*)d_out;

    float* base = nullptr;
    cudaGetSymbolAddress((void**)&base, g_scratch);
    const size_t T = TSLICE;

    bf* xh  = (bf*)base;            bf* xl  = xh + T;          // [0, T)
    bf* qb  = (bf*)(base + T);                                  // [T, 1.5T)
    bf* kb  = (bf*)(base + T + T / 2);                          // [1.5T, 2T)
    bf* vb  = (bf*)(base + 2 * T);                              // [2T, 2.5T)
    bf* ath = (bf*)(base + 2 * T + T / 2);                      // [2.5T, 3T)
    float* res = base + 3 * T + T / 2;                          // [3.5T, 4.5T)
    float* ln1 = base + 4 * T + T / 2;                          // [4.5T, 5.5T)
    bf* l1h = (bf*)(base + 5 * T + T / 2);                      // [5.5T, 6T)
    bf* fh  = (bf*)(base + 6 * T + T / 2);                      // [6.5T, 6.5T+FSLICE/2)
    float* wc = base + 6 * T + T / 2 + FSLICE;
    bf* wqh = (bf*)wc;            bf* wql = wqh + 65536;  wc += 65536;
    bf* wkh = (bf*)wc;            bf* wkl = wkh + 65536;  wc += 65536;
    bf* wvh = (bf*)wc;            bf* wvl = wvh + 65536;  wc += 65536;
    bf* woh = (bf*)wc;            bf* wol = woh + 65536;  wc += 65536;
    bf* w1h = (bf*)wc;            bf* w1l = w1h + 524288; wc += 524288;
    bf* w2h = (bf*)wc;            bf* w2l = w2h + 524288; wc += 524288;

    const int M = MTOK;
    const int mt = (M + 127) / 128;

    // batched operand splits (x + 6 weight matrices) in one launch
    SplitArgs sa;
    sa.in[0] = (const float4*)x;  sa.hi[0] = (uint32_t*)xh;  sa.lo[0] = (uint32_t*)xl;
    sa.in[1] = (const float4*)Wq; sa.hi[1] = (uint32_t*)wqh; sa.lo[1] = (uint32_t*)wql;
    sa.in[2] = (const float4*)Wk; sa.hi[2] = (uint32_t*)wkh; sa.lo[2] = (uint32_t*)wkl;
    sa.in[3] = (const float4*)Wv; sa.hi[3] = (uint32_t*)wvh; sa.lo[3] = (uint32_t*)wvl;
    sa.in[4] = (const float4*)Wo; sa.hi[4] = (uint32_t*)woh; sa.lo[4] = (uint32_t*)wol;
    sa.in[5] = (const float4*)W1; sa.hi[5] = (uint32_t*)w1h; sa.lo[5] = (uint32_t*)w1l;
    sa.in[6] = (const float4*)W2; sa.hi[6] = (uint32_t*)w2h; sa.lo[6] = (uint32_t*)w2l;
    int xs = (int)(T / 4);
    sa.start[0] = 0;
    sa.start[1] = xs;
    sa.start[2] = xs + 16384;
    sa.start[3] = xs + 32768;
    sa.start[4] = xs + 49152;
    sa.start[5] = xs + 65536;
    sa.start[6] = xs + 65536 + 131072;
    sa.start[7] = xs + 65536 + 262144;
    split_all<<<(sa.start[7] + 255) / 256, 256>>>(sa);

    cudaFuncSetAttribute(gemm_qkv, cudaFuncAttributeMaxDynamicSharedMemorySize, GEMM_SMEM);
    cudaFuncSetAttribute(gemm_bf<0, false, true >, cudaFuncAttributeMaxDynamicSharedMemorySize, GEMM_SMEM);
    cudaFuncSetAttribute(gemm_bf<1, true,  false>, cudaFuncAttributeMaxDynamicSharedMemorySize, GEMM_SMEM);
    cudaFuncSetAttribute(attn_mma, cudaFuncAttributeMaxDynamicSharedMemorySize, AT_SMEM);

    // q scale: 1/sqrt(32) * log2(e)  (softmax uses exp2)
    const float qscale = 0.17677669529663687f * 1.4426950408889634f;

    // fused QKV (2-term: x-hi only) -> bf16 (q scaled)
    QKVArgs qa;
    qa.wh[0] = wqh; qa.wh[1] = wkh; qa.wh[2] = wvh;
    qa.wl[0] = wql; qa.wl[1] = wkl; qa.wl[2] = wvl;
    qa.bias[0] = bq; qa.bias[1] = bk; qa.bias[2] = bv;
    qa.out[0] = qb; qa.out[1] = kb; qa.out[2] = vb;
    qa.scale[0] = qscale; qa.scale[1] = 1.f; qa.scale[2] = 1.f;
    gemm_qkv<<<dim3(mt, 6), 256, GEMM_SMEM>>>(xh, qa, M);

    // attention -> single bf16
    attn_mma<<<16 * 12 * NHEAD, 352, AT_SMEM>>>(qb, kb, vb, ath);

    // O-proj (2-term) + residual(x) -> res fp32; LN1 -> ln1 + hi plane
    gemm_bf<0, false, true><<<dim3(mt, 2), 256, GEMM_SMEM>>>(ath, woh, wol, bo, x, res, M, DMODEL, DMODEL, 1.f);
    ln_k<true><<<M / 8, 256>>>(res, g1, be1, ln1, l1h);

    // FFN1 (2-term) -> single bf16 (relu); FFN2 (2-term) + residual(ln1) -> res; LN2 -> out
    gemm_bf<1, true,  false><<<dim3(mt, 16), 256, GEMM_SMEM>>>(l1h, w1h, w1l, b1, nullptr, fh, M, FDIM, DMODEL, 1.f);
    gemm_bf<0, false, true ><<<dim3(mt, 2), 256, GEMM_SMEM>>>(fh, w2h, w2l, b2, ln1, res, M, DMODEL, FDIM, 1.f);
    ln_k<false><<<M / 8, 256>>>(res, g2, be2, out, nullptr);

    (void)in_sizes; (void)n_in; (void)out_size;
}

// round 15
// speedup vs baseline: 1.3943x; 1.3675x over previous
#include <cuda_runtime.h>
#include <cuda_bf16.h>
#include <cstdint>

// Problem constants
#define MTOK   62400      // B*S*N
#define DMODEL 256
#define FDIM   2048
#define NHEAD  8
#define HD     32
#define NNODE  325
#define NPAD   336        // 21 * 16
#define NKT    21

#define TSLICE ((size_t)MTOK * DMODEL)     // 15,974,400
#define FSLICE ((size_t)MTOK * FDIM)       // 127,795,200
__device__ float g_scratch[7 * TSLICE + FSLICE];

typedef __nv_bfloat16 bf;

// ---------------------------------------------------------------------------
// PTX helpers
// ---------------------------------------------------------------------------
__device__ __forceinline__ uint32_t smem_u32(const void* p) {
    uint32_t a;
    asm("{ .reg .u64 t; cvta.to.shared.u64 t, %1; cvt.u32.u64 %0, t; }" : "=r"(a) : "l"(p));
    return a;
}
__device__ __forceinline__ void ldsm_x4(uint32_t* r, uint32_t addr) {
    asm volatile("ldmatrix.sync.aligned.m8n8.x4.shared.b16 {%0,%1,%2,%3}, [%4];"
                 : "=r"(r[0]), "=r"(r[1]), "=r"(r[2]), "=r"(r[3]) : "r"(addr));
}
__device__ __forceinline__ void ldsm_x4_t(uint32_t* r, uint32_t addr) {
    asm volatile("ldmatrix.sync.aligned.m8n8.x4.trans.shared.b16 {%0,%1,%2,%3}, [%4];"
                 : "=r"(r[0]), "=r"(r[1]), "=r"(r[2]), "=r"(r[3]) : "r"(addr));
}
__device__ __forceinline__ void mma_bf16(float* d, const uint32_t* a, const uint32_t* b) {
    asm volatile("mma.sync.aligned.m16n8k16.row.col.f32.bf16.bf16.f32 "
                 "{%0,%1,%2,%3}, {%4,%5,%6,%7}, {%8,%9}, {%0,%1,%2,%3};"
                 : "+f"(d[0]), "+f"(d[1]), "+f"(d[2]), "+f"(d[3])
                 : "r"(a[0]), "r"(a[1]), "r"(a[2]), "r"(a[3]), "r"(b[0]), "r"(b[1]));
}
__device__ __forceinline__ void cp16(uint32_t dst, const void* src, bool pred) {
    int sz = pred ? 16 : 0;
    asm volatile("cp.async.cg.shared.global [%0], [%1], 16, %2;"
                 :: "r"(dst), "l"(src), "r"(sz));
}
__device__ __forceinline__ void cp_commit() {
    asm volatile("cp.async.commit_group;" ::: "memory");
}
__device__ __forceinline__ void cp_wait1() {
    asm volatile("cp.async.wait_group 1;" ::: "memory");
}
__device__ __forceinline__ void split2(float x, float y, uint32_t& hi, uint32_t& lo) {
    __nv_bfloat162 h = __floats2bfloat162_rn(x, y);
    float2 hf = __bfloat1622float2(h);
    __nv_bfloat162 l = __floats2bfloat162_rn(x - hf.x, y - hf.y);
    hi = *reinterpret_cast<uint32_t*>(&h);
    lo = *reinterpret_cast<uint32_t*>(&l);
}

// ---------------------------------------------------------------------------
// Batched split: fp32 -> planar bf16 hi/lo for x + 6 weights in ONE launch.
// ---------------------------------------------------------------------------
struct SplitArgs {
    const float4* in[7];
    uint32_t* hi[7];
    uint32_t* lo[7];
    int start[8];
};
__global__ void split_all(SplitArgs a)
{
    int i = blockIdx.x * 256 + threadIdx.x;
    if (i >= a.start[7]) return;
    int seg = 0;
#pragma unroll
    for (int s = 1; s < 7; s++) if (i >= a.start[s]) seg = s;
    int loc = i - a.start[seg];
    float4 v = a.in[seg][loc];
    uint32_t h0, l0, h1, l1;
    split2(v.x, v.y, h0, l0);
    split2(v.z, v.w, h1, l1);
    a.hi[seg][loc * 2] = h0; a.hi[seg][loc * 2 + 1] = h1;
    a.lo[seg][loc * 2] = l0; a.lo[seg][loc * 2 + 1] = l1;
}

// ---------------------------------------------------------------------------
// HMMA GEMM body, 3-stage cp.async pipeline, ONE __syncthreads per chunk.
// Order per iter: wait(own groups) -> sync(publish) -> compute -> prefetch.
// CTA 128x128, BK=32, 8 warps 4x2, 2 CTAs/SM.
// ALO: A has lo plane (3-term). Else 2-term (ah*bh + ah*bl).
// Stage: [AH 10240 | (AL 10240) | BH 8704 | BL 8704]
// OUT: 0 = fp32; 1 = bf16 (scaled); 2 = bf16 hi/lo planes
// ---------------------------------------------------------------------------
template<int OUT, bool RELU, bool RESID, bool ALO>
__device__ __forceinline__ void
gemm_body(const bf* __restrict__ Ahi, const bf* __restrict__ Alo,
          const bf* __restrict__ Bhi, const bf* __restrict__ Blo,
          const float* __restrict__ bias, const float* __restrict__ R,
          void* __restrict__ out0, void* __restrict__ out1,
          int M, int N, int K, float scale, int m0, int n0, char* smem)
{
    constexpr uint32_t AL_OFF = 10240;
    constexpr uint32_t B_OFF  = ALO ? 20480u : 10240u;
    constexpr uint32_t BL_REL = 8704;
    constexpr uint32_t STSZ   = ALO ? 37888u : 27648u;

    const uint32_t sb = smem_u32(smem);
    const int tid  = threadIdx.x;
    const int wid  = tid >> 5;
    const int lane = tid & 31;

    const int m_base = (wid & 3) * 32;
    const int n_base = (wid >> 2) * 64;

    const int ar = tid >> 2, aseg = tid & 3;
    const int br = tid >> 4, bseg = tid & 15;

    auto copyStage = [&](uint32_t buf, int ic) {
        const int k0 = ic << 5;
        const uint32_t st = sb + buf * STSZ;
#pragma unroll
        for (int it = 0; it < 2; it++) {
            int r = ar + it * 64;
            bool ok = (m0 + r) < M;
            size_t off = (size_t)(m0 + r) * K + k0 + aseg * 8;
            uint32_t d = st + (uint32_t)(r * 80 + aseg * 16);
            cp16(d, Ahi + off, ok);
            if (ALO) cp16(d + AL_OFF, Alo + off, ok);
        }
#pragma unroll
        for (int it = 0; it < 2; it++) {
            int r = br + it * 16;
            size_t off = (size_t)(k0 + r) * N + n0 + bseg * 8;
            uint32_t d = st + B_OFF + (uint32_t)(r * 272 + bseg * 16);
            cp16(d, Bhi + off, true);
            cp16(d + BL_REL, Blo + off, true);
        }
        cp_commit();
    };

    const uint32_t a_off = (uint32_t)((m_base + (lane & 15)) * 80 + (lane >> 4) * 16);
    const uint32_t b_off = B_OFF + (uint32_t)((lane & 15) * 272 + (n_base + (lane >> 4) * 8) * 2);

    float acc[2][8][4];
#pragma unroll
    for (int mf = 0; mf < 2; mf++)
#pragma unroll
        for (int nf = 0; nf < 8; nf++)
#pragma unroll
            for (int i = 0; i < 4; i++) acc[mf][nf][i] = 0.f;

    const int NC = K >> 5;
    copyStage(0, 0);
    copyStage(1, 1);

    uint32_t buf = 0;
    for (int ic = 0; ic < NC; ic++) {
        cp_wait1();          // own groups: chunk ic copy complete (ic+1 in flight)
        __syncthreads();     // publish all threads' chunk-ic copies; retire compute of ic-1

        const uint32_t st = sb + buf * STSZ;
#pragma unroll
        for (int ks = 0; ks < 2; ks++) {
            uint32_t ah[2][4], al[2][4], bb[8][2];
#pragma unroll
            for (int mf = 0; mf < 2; mf++) {
                uint32_t addr = st + a_off + (uint32_t)(mf * 16 * 80 + ks * 32);
                ldsm_x4(ah[mf], addr);
                if (ALO) ldsm_x4(al[mf], addr + AL_OFF);
            }
            // B-hi fragments
#pragma unroll
            for (int p = 0; p < 4; p++) {
                uint32_t t[4];
                ldsm_x4_t(t, st + b_off + (uint32_t)(ks * 16 * 272 + p * 32));
                bb[2 * p][0] = t[0]; bb[2 * p][1] = t[1];
                bb[2 * p + 1][0] = t[2]; bb[2 * p + 1][1] = t[3];
            }
#pragma unroll
            for (int nf = 0; nf < 8; nf++)
#pragma unroll
                for (int mf = 0; mf < 2; mf++)
                    mma_bf16(acc[mf][nf], ah[mf], bb[nf]);
            if (ALO) {
#pragma unroll
                for (int nf = 0; nf < 8; nf++)
#pragma unroll
                    for (int mf = 0; mf < 2; mf++)
                        mma_bf16(acc[mf][nf], al[mf], bb[nf]);
            }
            // B-lo fragments reuse bb registers
#pragma unroll
            for (int p = 0; p < 4; p++) {
                uint32_t t[4];
                ldsm_x4_t(t, st + b_off + (uint32_t)(ks * 16 * 272 + p * 32) + BL_REL);
                bb[2 * p][0] = t[0]; bb[2 * p][1] = t[1];
                bb[2 * p + 1][0] = t[2]; bb[2 * p + 1][1] = t[3];
            }
#pragma unroll
            for (int nf = 0; nf < 8; nf++)
#pragma unroll
                for (int mf = 0; mf < 2; mf++)
                    mma_bf16(acc[mf][nf], ah[mf], bb[nf]);
        }

        // prefetch chunk ic+2 into buffer (buf+2)%3 (= buffer of chunk ic-1,
        // retired by this iteration's barrier). Empty commit keeps the
        // one-group-per-iteration invariant for cp_wait1.
        if (ic + 2 < NC) copyStage((buf + 2 >= 3) ? buf - 1 : buf + 2, ic + 2);
        else cp_commit();

        buf = (buf == 2) ? 0 : buf + 1;
    }

    auto emit = [&](int row, int c, float v0, float v1) {
        size_t off = (size_t)row * N + c;
        v0 += bias[c]; v1 += bias[c + 1];
        if (RESID) { float2 rv = *(const float2*)(R + off); v0 += rv.x; v1 += rv.y; }
        if (RELU)  { v0 = fmaxf(v0, 0.f); v1 = fmaxf(v1, 0.f); }
        if (OUT == 0) {
            *(float2*)((float*)out0 + off) = make_float2(v0, v1);
        } else if (OUT == 1) {
            v0 *= scale; v1 *= scale;
            __nv_bfloat162 h = __floats2bfloat162_rn(v0, v1);
            *(__nv_bfloat162*)((bf*)out0 + off) = h;
        } else {
            __nv_bfloat162 h = __floats2bfloat162_rn(v0, v1);
            float2 hf = __bfloat1622float2(h);
            __nv_bfloat162 l = __floats2bfloat162_rn(v0 - hf.x, v1 - hf.y);
            *(__nv_bfloat162*)((bf*)out0 + off) = h;
            *(__nv_bfloat162*)((bf*)out1 + off) = l;
        }
    };
#pragma unroll
    for (int mf = 0; mf < 2; mf++) {
        const int r0 = m0 + m_base + mf * 16 + (lane >> 2);
#pragma unroll
        for (int nf = 0; nf < 8; nf++) {
            const int c = n0 + n_base + nf * 8 + (lane & 3) * 2;
            if (r0 < M)     emit(r0,     c, acc[mf][nf][0], acc[mf][nf][1]);
            if (r0 + 8 < M) emit(r0 + 8, c, acc[mf][nf][2], acc[mf][nf][3]);
        }
    }
}

#define SMEM_3T (3 * 37888)
#define SMEM_2T (3 * 27648)

template<int OUT, bool RELU, bool RESID, bool ALO>
__global__ void __launch_bounds__(256, 2)
gemm_bf(const bf* __restrict__ Ahi, const bf* __restrict__ Alo,
        const bf* __restrict__ Bhi, const bf* __restrict__ Blo,
        const float* __restrict__ bias, const float* __restrict__ R,
        void* __restrict__ out0, void* __restrict__ out1,
        int M, int N, int K, float scale)
{
    extern __shared__ char smem[];
    gemm_body<OUT, RELU, RESID, ALO>(Ahi, Alo, Bhi, Blo, bias, R, out0, out1,
                                     M, N, K, scale, blockIdx.x * 128, blockIdx.y * 128, smem);
}

// Fused QKV: grid.y in [0,6); weight = y>>1, n-tile = y&1. 2-term (x-hi only).
struct QKVArgs {
    const bf* wh[3]; const bf* wl[3];
    const float* bias[3];
    bf* out[3];
    float scale[3];
};
__global__ void __launch_bounds__(256, 2)
gemm_qkv(const bf* __restrict__ Ahi, QKVArgs args, int M)
{
    extern __shared__ char smem[];
    const int sel = blockIdx.y >> 1;
    const int n0  = (blockIdx.y & 1) * 128;
    gemm_body<1, false, false, false>(Ahi, nullptr, args.wh[sel], args.wl[sel],
                                      args.bias[sel], nullptr, args.out[sel], nullptr,
                                      M, DMODEL, DMODEL, args.scale[sel],
                                      blockIdx.x * 128, n0, smem);
}

// ---------------------------------------------------------------------------
// Tensor-core flash attention, no-max softmax, exp2-folded Q scale.
// Output: single bf16.
// ---------------------------------------------------------------------------
#define AT_K_OFF 28160
#define AT_V_OFF 55040
#define AT_SMEM  81920

__global__ void __launch_bounds__(352)
attn_mma(const bf* __restrict__ qg, const bf* __restrict__ kg,
         const bf* __restrict__ vg, bf* __restrict__ og)
{
    extern __shared__ char smem[];
    const uint32_t sb = smem_u32(smem);
    const int h  = blockIdx.x & (NHEAD - 1);
    const int bs = blockIdx.x >> 3;
    const int base = bs * NNODE;
    const int tid = threadIdx.x, lane = tid & 31, w = tid >> 5;

    for (int idx = tid; idx < 352 * 4; idx += 352) {
        int r = idx >> 2, seg = idx & 3;
        uint4 v = make_uint4(0, 0, 0, 0);
        if (r < NNODE)
            v = *(const uint4*)(qg + (size_t)(base + r) * DMODEL + h * HD + seg * 8);
        *(uint4*)(smem + r * 80 + seg * 16) = v;
    }
    for (int idx = tid; idx < NPAD * 4; idx += 352) {
        int r = idx >> 2, seg = idx & 3;
        uint4 kv = make_uint4(0, 0, 0, 0), vv = make_uint4(0, 0, 0, 0);
        if (r < NNODE) {
            kv = *(const uint4*)(kg + (size_t)(base + r) * DMODEL + h * HD + seg * 8);
            vv = *(const uint4*)(vg + (size_t)(base + r) * DMODEL + h * HD + seg * 8);
        }
        *(uint4*)(smem + AT_K_OFF + r * 80 + seg * 16) = kv;
        *(uint4*)(smem + AT_V_OFF + r * 80 + seg * 16) = vv;
    }
    __syncthreads();

    const int m_base = w * 32;
    uint32_t qf[2][2][4];
#pragma unroll
    for (int mf = 0; mf < 2; mf++)
#pragma unroll
        for (int kf = 0; kf < 2; kf++)
            ldsm_x4(qf[mf][kf],
                    sb + (uint32_t)((m_base + mf * 16 + (lane & 15)) * 80
                                    + kf * 32 + (lane >> 4) * 16));

    float o[2][4][4];
#pragma unroll
    for (int mf = 0; mf < 2; mf++)
#pragma unroll
        for (int nh = 0; nh < 4; nh++)
#pragma unroll
            for (int i = 0; i < 4; i++) o[mf][nh][i] = 0.f;
    float l[4] = {0.f, 0.f, 0.f, 0.f};

    for (int kt = 0; kt < NKT; kt++) {
        uint32_t kb[2][2][2];
#pragma unroll
        for (int kf = 0; kf < 2; kf++) {
            uint32_t t[4];
            ldsm_x4(t, sb + AT_K_OFF
                       + (uint32_t)((kt * 16 + (lane & 15)) * 80 + kf * 32 + (lane >> 4) * 16));
            kb[kf][0][0] = t[0]; kb[kf][0][1] = t[2];
            kb[kf][1][0] = t[1]; kb[kf][1][1] = t[3];
        }
        float s[2][2][4];
#pragma unroll
        for (int mf = 0; mf < 2; mf++)
#pragma unroll
            for (int nf = 0; nf < 2; nf++) {
#pragma unroll
                for (int i = 0; i < 4; i++) s[mf][nf][i] = 0.f;
#pragma unroll
                for (int kf = 0; kf < 2; kf++)
                    mma_bf16(s[mf][nf], qf[mf][kf], kb[kf][nf]);
            }
        if (kt == NKT - 1) {
#pragma unroll
            for (int nf = 0; nf < 2; nf++)
#pragma unroll
                for (int j = 0; j < 4; j++) {
                    int col = kt * 16 + nf * 8 + (lane & 3) * 2 + (j & 1);
                    if (col >= NNODE) { s[0][nf][j] = -1e30f; s[1][nf][j] = -1e30f; }
                }
        }
        uint32_t pa[2][4];
#pragma unroll
        for (int mf = 0; mf < 2; mf++) {
#pragma unroll
            for (int half = 0; half < 2; half++) {
                const int slot = mf * 2 + half;
                float p0 = exp2f(s[mf][0][half * 2]);
                float p1 = exp2f(s[mf][0][half * 2 + 1]);
                float p2 = exp2f(s[mf][1][half * 2]);
                float p3 = exp2f(s[mf][1][half * 2 + 1]);
                l[slot] += (p0 + p1) + (p2 + p3);
                s[mf][0][half * 2] = p0; s[mf][0][half * 2 + 1] = p1;
                s[mf][1][half * 2] = p2; s[mf][1][half * 2 + 1] = p3;
            }
            __nv_bfloat162 t;
            t = __floats2bfloat162_rn(s[mf][0][0], s[mf][0][1]); pa[mf][0] = *(uint32_t*)&t;
            t = __floats2bfloat162_rn(s[mf][0][2], s[mf][0][3]); pa[mf][1] = *(uint32_t*)&t;
            t = __floats2bfloat162_rn(s[mf][1][0], s[mf][1][1]); pa[mf][2] = *(uint32_t*)&t;
            t = __floats2bfloat162_rn(s[mf][1][2], s[mf][1][3]); pa[mf][3] = *(uint32_t*)&t;
        }
        uint32_t vf[4][2];
#pragma unroll
        for (int vh = 0; vh < 2; vh++) {
            uint32_t t[4];
            ldsm_x4_t(t, sb + AT_V_OFF
                         + (uint32_t)((kt * 16 + (lane & 15)) * 80 + vh * 32 + (lane >> 4) * 16));
            vf[2 * vh][0] = t[0]; vf[2 * vh][1] = t[1];
            vf[2 * vh + 1][0] = t[2]; vf[2 * vh + 1][1] = t[3];
        }
#pragma unroll
        for (int mf = 0; mf < 2; mf++)
#pragma unroll
            for (int nh = 0; nh < 4; nh++)
                mma_bf16(o[mf][nh], pa[mf], vf[nh]);
    }

#pragma unroll
    for (int slot = 0; slot < 4; slot++) {
        l[slot] += __shfl_xor_sync(0xffffffffu, l[slot], 1);
        l[slot] += __shfl_xor_sync(0xffffffffu, l[slot], 2);
        l[slot] = 1.f / l[slot];
    }
#pragma unroll
    for (int mf = 0; mf < 2; mf++)
#pragma unroll
        for (int half = 0; half < 2; half++) {
            const int slot = mf * 2 + half;
            const int r = m_base + mf * 16 + half * 8 + (lane >> 2);
            if (r >= NNODE) continue;
            const size_t rowoff = (size_t)(base + r) * DMODEL + h * HD;
#pragma unroll
            for (int nh = 0; nh < 4; nh++) {
                const int c = nh * 8 + (lane & 3) * 2;
                float v0 = o[mf][nh][half * 2] * l[slot];
                float v1 = o[mf][nh][half * 2 + 1] * l[slot];
                __nv_bfloat162 hh = __floats2bfloat162_rn(v0, v1);
                *(__nv_bfloat162*)(og + rowoff + c) = hh;
            }
        }
}

// ---------------------------------------------------------------------------
// LayerNorm; optionally also emit bf16 hi/lo planes of the output.
// ---------------------------------------------------------------------------
template<bool PLANES>
__global__ void __launch_bounds__(256)
ln_k(const float* __restrict__ in, const float* __restrict__ g,
     const float* __restrict__ bt, float* __restrict__ out,
     bf* __restrict__ phi, bf* __restrict__ plo)
{
    const int lane = threadIdx.x & 31;
    const int w    = threadIdx.x >> 5;
    const size_t row = (size_t)blockIdx.x * 8 + w;

    const float4* r = (const float4*)(in + row * DMODEL);
    float4 a = r[lane * 2], b = r[lane * 2 + 1];
    float s = a.x + a.y + a.z + a.w + b.x + b.y + b.z + b.w;
    float qs = a.x * a.x + a.y * a.y + a.z * a.z + a.w * a.w +
               b.x * b.x + b.y * b.y + b.z * b.z + b.w * b.w;
#pragma unroll
    for (int off = 16; off; off >>= 1) {
        s  += __shfl_xor_sync(0xffffffffu, s,  off);
        qs += __shfl_xor_sync(0xffffffffu, qs, off);
    }
    const float mean = s * (1.f / DMODEL);
    const float var  = qs * (1.f / DMODEL) - mean * mean;
    const float rstd = rsqrtf(var + 1e-5f);

    const float4* gv = (const float4*)g;
    const float4* bv = (const float4*)bt;
    float4 g0 = gv[lane * 2], g1 = gv[lane * 2 + 1];
    float4 b0 = bv[lane * 2], b1 = bv[lane * 2 + 1];

    float4 o0, o1;
    o0.x = (a.x - mean) * rstd * g0.x + b0.x;
    o0.y = (a.y - mean) * rstd * g0.y + b0.y;
    o0.z = (a.z - mean) * rstd * g0.z + b0.z;
    o0.w = (a.w - mean) * rstd * g0.w + b0.w;
    o1.x = (b.x - mean) * rstd * g1.x + b1.x;
    o1.y = (b.y - mean) * rstd * g1.y + b1.y;
    o1.z = (b.z - mean) * rstd * g1.z + b1.z;
    o1.w = (b.w - mean) * rstd * g1.w + b1.w;

    float4* op = (float4*)(out + row * DMODEL);
    op[lane * 2]     = o0;
    op[lane * 2 + 1] = o1;

    if (PLANES) {
        uint32_t h0, l0, h1, l1, h2, l2, h3, l3;
        split2(o0.x, o0.y, h0, l0);
        split2(o0.z, o0.w, h1, l1);
        split2(o1.x, o1.y, h2, l2);
        split2(o1.z, o1.w, h3, l3);
        uint4* ph = (uint4*)(phi + row * DMODEL);
        uint4* pl = (uint4*)(plo + row * DMODEL);
        ph[lane] = make_uint4(h0, h1, h2, h3);
        pl[lane] = make_uint4(l0, l1, l2, l3);
    }
}

// ---------------------------------------------------------------------------
// Launch
// ---------------------------------------------------------------------------
extern "C" void kernel_launch(void* const* d_in, const int* in_sizes, int n_in,
                              void* d_out, int out_size)
{
    const float* x   = (const float*)d_in[0];
    const float* Wq  = (const float*)d_in[1];
    const float* bq  = (const float*)d_in[2];
    const float* Wk  = (const float*)d_in[3];
    const float* bk  = (const float*)d_in[4];
    const float* Wv  = (const float*)d_in[5];
    const float* bv  = (const float*)d_in[6];
    const float* Wo  = (const float*)d_in[7];
    const float* bo  = (const float*)d_in[8];
    const float* W1  = (const float*)d_in[9];
    const float* b1  = (const float*)d_in[10];
    const float* W2  = (const float*)d_in[11];
    const float* b2  = (const float*)d_in[12];
    const float* g1  = (const float*)d_in[13];
    const float* be1 = (const float*)d_in[14];
    const float* g2  = (const float*)d_in[15];
    const float* be2 = (const float*)d_in[16];
    float* out = (float*)d_out;

    float* base = nullptr;
    cudaGetSymbolAddress((void**)&base, g_scratch);
    const size_t T = TSLICE;

    bf* xh  = (bf*)base;            bf* xl  = xh + T;          // [0, T)
    bf* qb  = (bf*)(base + T);                                  // [T, 1.5T)
    bf* kb  = (bf*)(base + T + T / 2);                          // [1.5T, 2T)
    bf* vb  = (bf*)(base + 2 * T);                              // [2T, 2.5T)
    bf* ath = (bf*)(base + 2 * T + T / 2);                      // [2.5T, 3T)
    float* res = base + 3 * T + T / 2;                          // [3.5T, 4.5T)
    float* ln1 = base + 4 * T + T / 2;                          // [4.5T, 5.5T)
    bf* l1h = (bf*)(base + 5 * T + T / 2); bf* l1l = l1h + T;   // [5.5T, 6.5T)
    bf* fh  = (bf*)(base + 6 * T + T / 2);                      // [6.5T, 6.5T+FSLICE/2)
    float* wc = base + 6 * T + T / 2 + FSLICE;
    bf* wqh = (bf*)wc;            bf* wql = wqh + 65536;  wc += 65536;
    bf* wkh = (bf*)wc;            bf* wkl = wkh + 65536;  wc += 65536;
    bf* wvh = (bf*)wc;            bf* wvl = wvh + 65536;  wc += 65536;
    bf* woh = (bf*)wc;            bf* wol = woh + 65536;  wc += 65536;
    bf* w1h = (bf*)wc;            bf* w1l = w1h + 524288; wc += 524288;
    bf* w2h = (bf*)wc;            bf* w2l = w2h + 524288; wc += 524288;

    const int M = MTOK;
    const int mt = (M + 127) / 128;

    // batched operand splits (x + 6 weight matrices) in one launch
    SplitArgs sa;
    sa.in[0] = (const float4*)x;  sa.hi[0] = (uint32_t*)xh;  sa.lo[0] = (uint32_t*)xl;
    sa.in[1] = (const float4*)Wq; sa.hi[1] = (uint32_t*)wqh; sa.lo[1] = (uint32_t*)wql;
    sa.in[2] = (const float4*)Wk; sa.hi[2] = (uint32_t*)wkh; sa.lo[2] = (uint32_t*)wkl;
    sa.in[3] = (const float4*)Wv; sa.hi[3] = (uint32_t*)wvh; sa.lo[3] = (uint32_t*)wvl;
    sa.in[4] = (const float4*)Wo; sa.hi[4] = (uint32_t*)woh; sa.lo[4] = (uint32_t*)wol;
    sa.in[5] = (const float4*)W1; sa.hi[5] = (uint32_t*)w1h; sa.lo[5] = (uint32_t*)w1l;
    sa.in[6] = (const float4*)W2; sa.hi[6] = (uint32_t*)w2h; sa.lo[6] = (uint32_t*)w2l;
    int xs = (int)(T / 4);
    sa.start[0] = 0;
    sa.start[1] = xs;
    sa.start[2] = xs + 16384;
    sa.start[3] = xs + 32768;
    sa.start[4] = xs + 49152;
    sa.start[5] = xs + 65536;
    sa.start[6] = xs + 65536 + 131072;
    sa.start[7] = xs + 65536 + 262144;
    split_all<<<(sa.start[7] + 255) / 256, 256>>>(sa);

    cudaFuncSetAttribute(gemm_qkv, cudaFuncAttributeMaxDynamicSharedMemorySize, SMEM_2T);
    cudaFuncSetAttribute(gemm_bf<0, false, true,  false>, cudaFuncAttributeMaxDynamicSharedMemorySize, SMEM_2T);
    cudaFuncSetAttribute(gemm_bf<1, true,  false, true >, cudaFuncAttributeMaxDynamicSharedMemorySize, SMEM_3T);
    cudaFuncSetAttribute(attn_mma, cudaFuncAttributeMaxDynamicSharedMemorySize, AT_SMEM);

    // q scale: 1/sqrt(32) * log2(e)  (softmax uses exp2)
    const float qscale = 0.17677669529663687f * 1.4426950408889634f;

    // fused QKV (2-term: x-hi only) -> bf16 (q scaled)
    QKVArgs qa;
    qa.wh[0] = wqh; qa.wh[1] = wkh; qa.wh[2] = wvh;
    qa.wl[0] = wql; qa.wl[1] = wkl; qa.wl[2] = wvl;
    qa.bias[0] = bq; qa.bias[1] = bk; qa.bias[2] = bv;
    qa.out[0] = qb; qa.out[1] = kb; qa.out[2] = vb;
    qa.scale[0] = qscale; qa.scale[1] = 1.f; qa.scale[2] = 1.f;
    gemm_qkv<<<dim3(mt, 6), 256, SMEM_2T>>>(xh, qa, M);

    // attention -> single bf16
    attn_mma<<<16 * 12 * NHEAD, 352, AT_SMEM>>>(qb, kb, vb, ath);

    // O-proj (2-term) + residual(x) -> res fp32; LN1 -> ln1 + hi/lo planes
    gemm_bf<0, false, true, false><<<dim3(mt, 2), 256, SMEM_2T>>>(ath, nullptr, woh, wol, bo, x, res, nullptr, M, DMODEL, DMODEL, 1.f);
    ln_k<true><<<M / 8, 256>>>(res, g1, be1, ln1, l1h, l1l);

    // FFN1 (3-term) -> single bf16 (relu); FFN2 (2-term) + residual(ln1) -> res; LN2 -> out
    gemm_bf<1, true,  false, true ><<<dim3(mt, 16), 256, SMEM_3T>>>(l1h, l1l, w1h, w1l, b1, nullptr, fh, nullptr, M, FDIM, DMODEL, 1.f);
    gemm_bf<0, false, true,  false><<<dim3(mt, 2), 256, SMEM_2T>>>(fh, nullptr, w2h, w2l, b2, ln1, res, nullptr, M, DMODEL, FDIM, 1.f);
    ln_k<false><<<M / 8, 256>>>(res, g2, be2, out, nullptr, nullptr);

    (void)in_sizes; (void)n_in; (void)out_size;
}

// round 16
// speedup vs baseline: 1.5555x; 1.1156x over previous
#include <cuda_runtime.h>
#include <cuda_bf16.h>
#include <cstdint>

// Problem constants
#define MTOK   62400      // B*S*N
#define DMODEL 256
#define FDIM   2048
#define NHEAD  8
#define HD     32
#define NNODE  325
#define NPAD   336        // 21 * 16
#define NKT    21

#define TSLICE ((size_t)MTOK * DMODEL)     // 15,974,400
#define FSLICE ((size_t)MTOK * FDIM)       // 127,795,200
__device__ float g_scratch[7 * TSLICE + FSLICE];

typedef __nv_bfloat16 bf;

// ---------------------------------------------------------------------------
// PTX helpers
// ---------------------------------------------------------------------------
__device__ __forceinline__ uint32_t smem_u32(const void* p) {
    uint32_t a;
    asm("{ .reg .u64 t; cvta.to.shared.u64 t, %1; cvt.u32.u64 %0, t; }" : "=r"(a) : "l"(p));
    return a;
}
__device__ __forceinline__ void ldsm_x4(uint32_t* r, uint32_t addr) {
    asm volatile("ldmatrix.sync.aligned.m8n8.x4.shared.b16 {%0,%1,%2,%3}, [%4];"
                 : "=r"(r[0]), "=r"(r[1]), "=r"(r[2]), "=r"(r[3]) : "r"(addr));
}
__device__ __forceinline__ void ldsm_x4_t(uint32_t* r, uint32_t addr) {
    asm volatile("ldmatrix.sync.aligned.m8n8.x4.trans.shared.b16 {%0,%1,%2,%3}, [%4];"
                 : "=r"(r[0]), "=r"(r[1]), "=r"(r[2]), "=r"(r[3]) : "r"(addr));
}
__device__ __forceinline__ void mma_bf16(float* d, const uint32_t* a, const uint32_t* b) {
    asm volatile("mma.sync.aligned.m16n8k16.row.col.f32.bf16.bf16.f32 "
                 "{%0,%1,%2,%3}, {%4,%5,%6,%7}, {%8,%9}, {%0,%1,%2,%3};"
                 : "+f"(d[0]), "+f"(d[1]), "+f"(d[2]), "+f"(d[3])
                 : "r"(a[0]), "r"(a[1]), "r"(a[2]), "r"(a[3]), "r"(b[0]), "r"(b[1]));
}
__device__ __forceinline__ void cp16(uint32_t dst, const void* src, bool pred) {
    int sz = pred ? 16 : 0;
    asm volatile("cp.async.cg.shared.global [%0], [%1], 16, %2;"
                 :: "r"(dst), "l"(src), "r"(sz));
}
__device__ __forceinline__ void cp_commit() {
    asm volatile("cp.async.commit_group;" ::: "memory");
}
__device__ __forceinline__ void cp_wait1() {
    asm volatile("cp.async.wait_group 1;" ::: "memory");
}
__device__ __forceinline__ void split2(float x, float y, uint32_t& hi, uint32_t& lo) {
    __nv_bfloat162 h = __floats2bfloat162_rn(x, y);
    float2 hf = __bfloat1622float2(h);
    __nv_bfloat162 l = __floats2bfloat162_rn(x - hf.x, y - hf.y);
    hi = *reinterpret_cast<uint32_t*>(&h);
    lo = *reinterpret_cast<uint32_t*>(&l);
}

// ---------------------------------------------------------------------------
// Batched split: fp32 -> planar bf16 hi/lo for x + 6 weights in ONE launch.
// ---------------------------------------------------------------------------
struct SplitArgs {
    const float4* in[7];
    uint32_t* hi[7];
    uint32_t* lo[7];
    int start[8];
};
__global__ void split_all(SplitArgs a)
{
    int i = blockIdx.x * 256 + threadIdx.x;
    if (i >= a.start[7]) return;
    int seg = 0;
#pragma unroll
    for (int s = 1; s < 7; s++) if (i >= a.start[s]) seg = s;
    int loc = i - a.start[seg];
    float4 v = a.in[seg][loc];
    uint32_t h0, l0, h1, l1;
    split2(v.x, v.y, h0, l0);
    split2(v.z, v.w, h1, l1);
    a.hi[seg][loc * 2] = h0; a.hi[seg][loc * 2 + 1] = h1;
    a.lo[seg][loc * 2] = l0; a.lo[seg][loc * 2 + 1] = l1;
}

// ---------------------------------------------------------------------------
// HMMA GEMM body, 3-stage cp.async pipeline, ONE __syncthreads per chunk.
// Order per iter: wait(own groups) -> sync(publish) -> compute -> prefetch.
// CTA 128x128, BK=32, 8 warps 4x2, 2 CTAs/SM.
// ALO: A has lo plane (3-term). Else 2-term (ah*bh + ah*bl).
// Stage: [AH 10240 | (AL 10240) | BH 8704 | BL 8704]
// OUT: 0 = fp32; 1 = bf16 (scaled); 2 = bf16 hi/lo planes
// ---------------------------------------------------------------------------
template<int OUT, bool RELU, bool RESID, bool ALO>
__device__ __forceinline__ void
gemm_body(const bf* __restrict__ Ahi, const bf* __restrict__ Alo,
          const bf* __restrict__ Bhi, const bf* __restrict__ Blo,
          const float* __restrict__ bias, const float* __restrict__ R,
          void* __restrict__ out0, void* __restrict__ out1,
          int M, int N, int K, float scale, int m0, int n0, char* smem)
{
    constexpr uint32_t AL_OFF = 10240;
    constexpr uint32_t B_OFF  = ALO ? 20480u : 10240u;
    constexpr uint32_t BL_REL = 8704;
    constexpr uint32_t STSZ   = ALO ? 37888u : 27648u;

    const uint32_t sb = smem_u32(smem);
    const int tid  = threadIdx.x;
    const int wid  = tid >> 5;
    const int lane = tid & 31;

    const int m_base = (wid & 3) * 32;
    const int n_base = (wid >> 2) * 64;

    const int ar = tid >> 2, aseg = tid & 3;
    const int br = tid >> 4, bseg = tid & 15;

    auto copyStage = [&](uint32_t buf, int ic) {
        const int k0 = ic << 5;
        const uint32_t st = sb + buf * STSZ;
#pragma unroll
        for (int it = 0; it < 2; it++) {
            int r = ar + it * 64;
            bool ok = (m0 + r) < M;
            size_t off = (size_t)(m0 + r) * K + k0 + aseg * 8;
            uint32_t d = st + (uint32_t)(r * 80 + aseg * 16);
            cp16(d, Ahi + off, ok);
            if (ALO) cp16(d + AL_OFF, Alo + off, ok);
        }
#pragma unroll
        for (int it = 0; it < 2; it++) {
            int r = br + it * 16;
            size_t off = (size_t)(k0 + r) * N + n0 + bseg * 8;
            uint32_t d = st + B_OFF + (uint32_t)(r * 272 + bseg * 16);
            cp16(d, Bhi + off, true);
            cp16(d + BL_REL, Blo + off, true);
        }
        cp_commit();
    };

    const uint32_t a_off = (uint32_t)((m_base + (lane & 15)) * 80 + (lane >> 4) * 16);
    const uint32_t b_off = B_OFF + (uint32_t)((lane & 15) * 272 + (n_base + (lane >> 4) * 8) * 2);

    float acc[2][8][4];
#pragma unroll
    for (int mf = 0; mf < 2; mf++)
#pragma unroll
        for (int nf = 0; nf < 8; nf++)
#pragma unroll
            for (int i = 0; i < 4; i++) acc[mf][nf][i] = 0.f;

    const int NC = K >> 5;
    copyStage(0, 0);
    copyStage(1, 1);

    uint32_t buf = 0;
    for (int ic = 0; ic < NC; ic++) {
        cp_wait1();          // own groups: chunk ic copy complete (ic+1 in flight)
        __syncthreads();     // publish all threads' chunk-ic copies; retire compute of ic-1

        const uint32_t st = sb + buf * STSZ;
#pragma unroll
        for (int ks = 0; ks < 2; ks++) {
            uint32_t ah[2][4], al[2][4], bb[8][2];
#pragma unroll
            for (int mf = 0; mf < 2; mf++) {
                uint32_t addr = st + a_off + (uint32_t)(mf * 16 * 80 + ks * 32);
                ldsm_x4(ah[mf], addr);
                if (ALO) ldsm_x4(al[mf], addr + AL_OFF);
            }
            // B-hi fragments
#pragma unroll
            for (int p = 0; p < 4; p++) {
                uint32_t t[4];
                ldsm_x4_t(t, st + b_off + (uint32_t)(ks * 16 * 272 + p * 32));
                bb[2 * p][0] = t[0]; bb[2 * p][1] = t[1];
                bb[2 * p + 1][0] = t[2]; bb[2 * p + 1][1] = t[3];
            }
#pragma unroll
            for (int nf = 0; nf < 8; nf++)
#pragma unroll
                for (int mf = 0; mf < 2; mf++)
                    mma_bf16(acc[mf][nf], ah[mf], bb[nf]);
            if (ALO) {
#pragma unroll
                for (int nf = 0; nf < 8; nf++)
#pragma unroll
                    for (int mf = 0; mf < 2; mf++)
                        mma_bf16(acc[mf][nf], al[mf], bb[nf]);
            }
            // B-lo fragments reuse bb registers
#pragma unroll
            for (int p = 0; p < 4; p++) {
                uint32_t t[4];
                ldsm_x4_t(t, st + b_off + (uint32_t)(ks * 16 * 272 + p * 32) + BL_REL);
                bb[2 * p][0] = t[0]; bb[2 * p][1] = t[1];
                bb[2 * p + 1][0] = t[2]; bb[2 * p + 1][1] = t[3];
            }
#pragma unroll
            for (int nf = 0; nf < 8; nf++)
#pragma unroll
                for (int mf = 0; mf < 2; mf++)
                    mma_bf16(acc[mf][nf], ah[mf], bb[nf]);
        }

        // prefetch chunk ic+2 into buffer (buf+2)%3 (= buffer of chunk ic-1,
        // retired by this iteration's barrier). Empty commit keeps the
        // one-group-per-iteration invariant for cp_wait1.
        if (ic + 2 < NC) copyStage((buf + 2 >= 3) ? buf - 1 : buf + 2, ic + 2);
        else cp_commit();

        buf = (buf == 2) ? 0 : buf + 1;
    }

    auto emit = [&](int row, int c, float v0, float v1) {
        size_t off = (size_t)row * N + c;
        v0 += bias[c]; v1 += bias[c + 1];
        if (RESID) { float2 rv = *(const float2*)(R + off); v0 += rv.x; v1 += rv.y; }
        if (RELU)  { v0 = fmaxf(v0, 0.f); v1 = fmaxf(v1, 0.f); }
        if (OUT == 0) {
            *(float2*)((float*)out0 + off) = make_float2(v0, v1);
        } else if (OUT == 1) {
            v0 *= scale; v1 *= scale;
            __nv_bfloat162 h = __floats2bfloat162_rn(v0, v1);
            *(__nv_bfloat162*)((bf*)out0 + off) = h;
        } else {
            __nv_bfloat162 h = __floats2bfloat162_rn(v0, v1);
            float2 hf = __bfloat1622float2(h);
            __nv_bfloat162 l = __floats2bfloat162_rn(v0 - hf.x, v1 - hf.y);
            *(__nv_bfloat162*)((bf*)out0 + off) = h;
            *(__nv_bfloat162*)((bf*)out1 + off) = l;
        }
    };
#pragma unroll
    for (int mf = 0; mf < 2; mf++) {
        const int r0 = m0 + m_base + mf * 16 + (lane >> 2);
#pragma unroll
        for (int nf = 0; nf < 8; nf++) {
            const int c = n0 + n_base + nf * 8 + (lane & 3) * 2;
            if (r0 < M)     emit(r0,     c, acc[mf][nf][0], acc[mf][nf][1]);
            if (r0 + 8 < M) emit(r0 + 8, c, acc[mf][nf][2], acc[mf][nf][3]);
        }
    }
}

#define SMEM_3T (3 * 37888)
#define SMEM_2T (3 * 27648)

template<int OUT, bool RELU, bool RESID, bool ALO>
__global__ void __launch_bounds__(256, 2)
gemm_bf(const bf* __restrict__ Ahi, const bf* __restrict__ Alo,
        const bf* __restrict__ Bhi, const bf* __restrict__ Blo,
        const float* __restrict__ bias, const float* __restrict__ R,
        void* __restrict__ out0, void* __restrict__ out1,
        int M, int N, int K, float scale)
{
    extern __shared__ char smem[];
    gemm_body<OUT, RELU, RESID, ALO>(Ahi, Alo, Bhi, Blo, bias, R, out0, out1,
                                     M, N, K, scale, blockIdx.x * 128, blockIdx.y * 128, smem);
}

// Fused QKV: grid.y in [0,6); weight = y>>1, n-tile = y&1. 2-term (x-hi only).
struct QKVArgs {
    const bf* wh[3]; const bf* wl[3];
    const float* bias[3];
    bf* out[3];
    float scale[3];
};
__global__ void __launch_bounds__(256, 2)
gemm_qkv(const bf* __restrict__ Ahi, QKVArgs args, int M)
{
    extern __shared__ char smem[];
    const int sel = blockIdx.y >> 1;
    const int n0  = (blockIdx.y & 1) * 128;
    gemm_body<1, false, false, false>(Ahi, nullptr, args.wh[sel], args.wl[sel],
                                      args.bias[sel], nullptr, args.out[sel], nullptr,
                                      M, DMODEL, DMODEL, args.scale[sel],
                                      blockIdx.x * 128, n0, smem);
}

// ---------------------------------------------------------------------------
// Tensor-core flash attention, no-max softmax, exp2-folded Q scale.
// Output: single bf16.
// ---------------------------------------------------------------------------
#define AT_K_OFF 28160
#define AT_V_OFF 55040
#define AT_SMEM  81920

__global__ void __launch_bounds__(352)
attn_mma(const bf* __restrict__ qg, const bf* __restrict__ kg,
         const bf* __restrict__ vg, bf* __restrict__ og)
{
    extern __shared__ char smem[];
    const uint32_t sb = smem_u32(smem);
    const int h  = blockIdx.x & (NHEAD - 1);
    const int bs = blockIdx.x >> 3;
    const int base = bs * NNODE;
    const int tid = threadIdx.x, lane = tid & 31, w = tid >> 5;

    for (int idx = tid; idx < 352 * 4; idx += 352) {
        int r = idx >> 2, seg = idx & 3;
        uint4 v = make_uint4(0, 0, 0, 0);
        if (r < NNODE)
            v = *(const uint4*)(qg + (size_t)(base + r) * DMODEL + h * HD + seg * 8);
        *(uint4*)(smem + r * 80 + seg * 16) = v;
    }
    for (int idx = tid; idx < NPAD * 4; idx += 352) {
        int r = idx >> 2, seg = idx & 3;
        uint4 kv = make_uint4(0, 0, 0, 0), vv = make_uint4(0, 0, 0, 0);
        if (r < NNODE) {
            kv = *(const uint4*)(kg + (size_t)(base + r) * DMODEL + h * HD + seg * 8);
            vv = *(const uint4*)(vg + (size_t)(base + r) * DMODEL + h * HD + seg * 8);
        }
        *(uint4*)(smem + AT_K_OFF + r * 80 + seg * 16) = kv;
        *(uint4*)(smem + AT_V_OFF + r * 80 + seg * 16) = vv;
    }
    __syncthreads();

    const int m_base = w * 32;
    uint32_t qf[2][2][4];
#pragma unroll
    for (int mf = 0; mf < 2; mf++)
#pragma unroll
        for (int kf = 0; kf < 2; kf++)
            ldsm_x4(qf[mf][kf],
                    sb + (uint32_t)((m_base + mf * 16 + (lane & 15)) * 80
                                    + kf * 32 + (lane >> 4) * 16));

    float o[2][4][4];
#pragma unroll
    for (int mf = 0; mf < 2; mf++)
#pragma unroll
        for (int nh = 0; nh < 4; nh++)
#pragma unroll
            for (int i = 0; i < 4; i++) o[mf][nh][i] = 0.f;
    float l[4] = {0.f, 0.f, 0.f, 0.f};

    for (int kt = 0; kt < NKT; kt++) {
        uint32_t kb[2][2][2];
#pragma unroll
        for (int kf = 0; kf < 2; kf++) {
            uint32_t t[4];
            ldsm_x4(t, sb + AT_K_OFF
                       + (uint32_t)((kt * 16 + (lane & 15)) * 80 + kf * 32 + (lane >> 4) * 16));
            kb[kf][0][0] = t[0]; kb[kf][0][1] = t[2];
            kb[kf][1][0] = t[1]; kb[kf][1][1] = t[3];
        }
        float s[2][2][4];
#pragma unroll
        for (int mf = 0; mf < 2; mf++)
#pragma unroll
            for (int nf = 0; nf < 2; nf++) {
#pragma unroll
                for (int i = 0; i < 4; i++) s[mf][nf][i] = 0.f;
#pragma unroll
                for (int kf = 0; kf < 2; kf++)
                    mma_bf16(s[mf][nf], qf[mf][kf], kb[kf][nf]);
            }
        if (kt == NKT - 1) {
#pragma unroll
            for (int nf = 0; nf < 2; nf++)
#pragma unroll
                for (int j = 0; j < 4; j++) {
                    int col = kt * 16 + nf * 8 + (lane & 3) * 2 + (j & 1);
                    if (col >= NNODE) { s[0][nf][j] = -1e30f; s[1][nf][j] = -1e30f; }
                }
        }
        uint32_t pa[2][4];
#pragma unroll
        for (int mf = 0; mf < 2; mf++) {
#pragma unroll
            for (int half = 0; half < 2; half++) {
                const int slot = mf * 2 + half;
                float p0 = exp2f(s[mf][0][half * 2]);
                float p1 = exp2f(s[mf][0][half * 2 + 1]);
                float p2 = exp2f(s[mf][1][half * 2]);
                float p3 = exp2f(s[mf][1][half * 2 + 1]);
                l[slot] += (p0 + p1) + (p2 + p3);
                s[mf][0][half * 2] = p0; s[mf][0][half * 2 + 1] = p1;
                s[mf][1][half * 2] = p2; s[mf][1][half * 2 + 1] = p3;
            }
            __nv_bfloat162 t;
            t = __floats2bfloat162_rn(s[mf][0][0], s[mf][0][1]); pa[mf][0] = *(uint32_t*)&t;
            t = __floats2bfloat162_rn(s[mf][0][2], s[mf][0][3]); pa[mf][1] = *(uint32_t*)&t;
            t = __floats2bfloat162_rn(s[mf][1][0], s[mf][1][1]); pa[mf][2] = *(uint32_t*)&t;
            t = __floats2bfloat162_rn(s[mf][1][2], s[mf][1][3]); pa[mf][3] = *(uint32_t*)&t;
        }
        uint32_t vf[4][2];
#pragma unroll
        for (int vh = 0; vh < 2; vh++) {
            uint32_t t[4];
            ldsm_x4_t(t, sb + AT_V_OFF
                         + (uint32_t)((kt * 16 + (lane & 15)) * 80 + vh * 32 + (lane >> 4) * 16));
            vf[2 * vh][0] = t[0]; vf[2 * vh][1] = t[1];
            vf[2 * vh + 1][0] = t[2]; vf[2 * vh + 1][1] = t[3];
        }
#pragma unroll
        for (int mf = 0; mf < 2; mf++)
#pragma unroll
            for (int nh = 0; nh < 4; nh++)
                mma_bf16(o[mf][nh], pa[mf], vf[nh]);
    }

#pragma unroll
    for (int slot = 0; slot < 4; slot++) {
        l[slot] += __shfl_xor_sync(0xffffffffu, l[slot], 1);
        l[slot] += __shfl_xor_sync(0xffffffffu, l[slot], 2);
        l[slot] = 1.f / l[slot];
    }
#pragma unroll
    for (int mf = 0; mf < 2; mf++)
#pragma unroll
        for (int half = 0; half < 2; half++) {
            const int slot = mf * 2 + half;
            const int r = m_base + mf * 16 + half * 8 + (lane >> 2);
            if (r >= NNODE) continue;
            const size_t rowoff = (size_t)(base + r) * DMODEL + h * HD;
#pragma unroll
            for (int nh = 0; nh < 4; nh++) {
                const int c = nh * 8 + (lane & 3) * 2;
                float v0 = o[mf][nh][half * 2] * l[slot];
                float v1 = o[mf][nh][half * 2 + 1] * l[slot];
                __nv_bfloat162 hh = __floats2bfloat162_rn(v0, v1);
                *(__nv_bfloat162*)(og + rowoff + c) = hh;
            }
        }
}

// ---------------------------------------------------------------------------
// LayerNorm; optionally also emit bf16 hi plane of the output.
// ---------------------------------------------------------------------------
template<bool PLANES>
__global__ void __launch_bounds__(256)
ln_k(const float* __restrict__ in, const float* __restrict__ g,
     const float* __restrict__ bt, float* __restrict__ out,
     bf* __restrict__ phi)
{
    const int lane = threadIdx.x & 31;
    const int w    = threadIdx.x >> 5;
    const size_t row = (size_t)blockIdx.x * 8 + w;

    const float4* r = (const float4*)(in + row * DMODEL);
    float4 a = r[lane * 2], b = r[lane * 2 + 1];
    float s = a.x + a.y + a.z + a.w + b.x + b.y + b.z + b.w;
    float qs = a.x * a.x + a.y * a.y + a.z * a.z + a.w * a.w +
               b.x * b.x + b.y * b.y + b.z * b.z + b.w * b.w;
#pragma unroll
    for (int off = 16; off; off >>= 1) {
        s  += __shfl_xor_sync(0xffffffffu, s,  off);
        qs += __shfl_xor_sync(0xffffffffu, qs, off);
    }
    const float mean = s * (1.f / DMODEL);
    const float var  = qs * (1.f / DMODEL) - mean * mean;
    const float rstd = rsqrtf(var + 1e-5f);

    const float4* gv = (const float4*)g;
    const float4* bv = (const float4*)bt;
    float4 g0 = gv[lane * 2], g1 = gv[lane * 2 + 1];
    float4 b0 = bv[lane * 2], b1 = bv[lane * 2 + 1];

    float4 o0, o1;
    o0.x = (a.x - mean) * rstd * g0.x + b0.x;
    o0.y = (a.y - mean) * rstd * g0.y + b0.y;
    o0.z = (a.z - mean) * rstd * g0.z + b0.z;
    o0.w = (a.w - mean) * rstd * g0.w + b0.w;
    o1.x = (b.x - mean) * rstd * g1.x + b1.x;
    o1.y = (b.y - mean) * rstd * g1.y + b1.y;
    o1.z = (b.z - mean) * rstd * g1.z + b1.z;
    o1.w = (b.w - mean) * rstd * g1.w + b1.w;

    float4* op = (float4*)(out + row * DMODEL);
    op[lane * 2]     = o0;
    op[lane * 2 + 1] = o1;

    if (PLANES) {
        __nv_bfloat162 h0 = __floats2bfloat162_rn(o0.x, o0.y);
        __nv_bfloat162 h1 = __floats2bfloat162_rn(o0.z, o0.w);
        __nv_bfloat162 h2 = __floats2bfloat162_rn(o1.x, o1.y);
        __nv_bfloat162 h3 = __floats2bfloat162_rn(o1.z, o1.w);
        uint4* ph = (uint4*)(phi + row * DMODEL);
        ph[lane] = make_uint4(*(uint32_t*)&h0, *(uint32_t*)&h1,
                              *(uint32_t*)&h2, *(uint32_t*)&h3);
    }
}

// ---------------------------------------------------------------------------
// Launch
// ---------------------------------------------------------------------------
extern "C" void kernel_launch(void* const* d_in, const int* in_sizes, int n_in,
                              void* d_out, int out_size)
{
    const float* x   = (const float*)d_in[0];
    const float* Wq  = (const float*)d_in[1];
    const float* bq  = (const float*)d_in[2];
    const float* Wk  = (const float*)d_in[3];
    const float* bk  = (const float*)d_in[4];
    const float* Wv  = (const float*)d_in[5];
    const float* bv  = (const float*)d_in[6];
    const float* Wo  = (const float*)d_in[7];
    const float* bo  = (const float*)d_in[8];
    const float* W1  = (const float*)d_in[9];
    const float* b1  = (const float*)d_in[10];
    const float* W2  = (const float*)d_in[11];
    const float* b2  = (const float*)d_in[12];
    const float* g1  = (const float*)d_in[13];
    const float* be1 = (const float*)d_in[14];
    const float* g2  = (const float*)d_in[15];
    const float* be2 = (const float*)d_in[16];
    float* out = (float*)d_out;

    float* base = nullptr;
    cudaGetSymbolAddress((void**)&base, g_scratch);
    const size_t T = TSLICE;

    bf* xh  = (bf*)base;            bf* xl  = xh + T;          // [0, T)
    bf* qb  = (bf*)(base + T);                                  // [T, 1.5T)
    bf* kb  = (bf*)(base + T + T / 2);                          // [1.5T, 2T)
    bf* vb  = (bf*)(base + 2 * T);                              // [2T, 2.5T)
    bf* ath = (bf*)(base + 2 * T + T / 2);                      // [2.5T, 3T)
    float* res = base + 3 * T + T / 2;                          // [3.5T, 4.5T)
    float* ln1 = base + 4 * T + T / 2;                          // [4.5T, 5.5T)
    bf* l1h = (bf*)(base + 5 * T + T / 2);                      // [5.5T, 6T)
    bf* fh  = (bf*)(base + 6 * T + T / 2);                      // [6.5T, 6.5T+FSLICE/2)
    float* wc = base + 6 * T + T / 2 + FSLICE;
    bf* wqh = (bf*)wc;            bf* wql = wqh + 65536;  wc += 65536;
    bf* wkh = (bf*)wc;            bf* wkl = wkh + 65536;  wc += 65536;
    bf* wvh = (bf*)wc;            bf* wvl = wvh + 65536;  wc += 65536;
    bf* woh = (bf*)wc;            bf* wol = woh + 65536;  wc += 65536;
    bf* w1h = (bf*)wc;            bf* w1l = w1h + 524288; wc += 524288;
    bf* w2h = (bf*)wc;            bf* w2l = w2h + 524288; wc += 524288;

    const int M = MTOK;
    const int mt = (M + 127) / 128;

    // batched operand splits (x + 6 weight matrices) in one launch
    SplitArgs sa;
    sa.in[0] = (const float4*)x;  sa.hi[0] = (uint32_t*)xh;  sa.lo[0] = (uint32_t*)xl;
    sa.in[1] = (const float4*)Wq; sa.hi[1] = (uint32_t*)wqh; sa.lo[1] = (uint32_t*)wql;
    sa.in[2] = (const float4*)Wk; sa.hi[2] = (uint32_t*)wkh; sa.lo[2] = (uint32_t*)wkl;
    sa.in[3] = (const float4*)Wv; sa.hi[3] = (uint32_t*)wvh; sa.lo[3] = (uint32_t*)wvl;
    sa.in[4] = (const float4*)Wo; sa.hi[4] = (uint32_t*)woh; sa.lo[4] = (uint32_t*)wol;
    sa.in[5] = (const float4*)W1; sa.hi[5] = (uint32_t*)w1h; sa.lo[5] = (uint32_t*)w1l;
    sa.in[6] = (const float4*)W2; sa.hi[6] = (uint32_t*)w2h; sa.lo[6] = (uint32_t*)w2l;
    int xs = (int)(T / 4);
    sa.start[0] = 0;
    sa.start[1] = xs;
    sa.start[2] = xs + 16384;
    sa.start[3] = xs + 32768;
    sa.start[4] = xs + 49152;
    sa.start[5] = xs + 65536;
    sa.start[6] = xs + 65536 + 131072;
    sa.start[7] = xs + 65536 + 262144;
    split_all<<<(sa.start[7] + 255) / 256, 256>>>(sa);

    cudaFuncSetAttribute(gemm_qkv, cudaFuncAttributeMaxDynamicSharedMemorySize, SMEM_2T);
    cudaFuncSetAttribute(gemm_bf<0, false, true,  false>, cudaFuncAttributeMaxDynamicSharedMemorySize, SMEM_2T);
    cudaFuncSetAttribute(gemm_bf<1, true,  false, false>, cudaFuncAttributeMaxDynamicSharedMemorySize, SMEM_2T);
    cudaFuncSetAttribute(attn_mma, cudaFuncAttributeMaxDynamicSharedMemorySize, AT_SMEM);

    // q scale: 1/sqrt(32) * log2(e)  (softmax uses exp2)
    const float qscale = 0.17677669529663687f * 1.4426950408889634f;

    // fused QKV (2-term: x-hi only) -> bf16 (q scaled)
    QKVArgs qa;
    qa.wh[0] = wqh; qa.wh[1] = wkh; qa.wh[2] = wvh;
    qa.wl[0] = wql; qa.wl[1] = wkl; qa.wl[2] = wvl;
    qa.bias[0] = bq; qa.bias[1] = bk; qa.bias[2] = bv;
    qa.out[0] = qb; qa.out[1] = kb; qa.out[2] = vb;
    qa.scale[0] = qscale; qa.scale[1] = 1.f; qa.scale[2] = 1.f;
    gemm_qkv<<<dim3(mt, 6), 256, SMEM_2T>>>(xh, qa, M);

    // attention -> single bf16
    attn_mma<<<16 * 12 * NHEAD, 352, AT_SMEM>>>(qb, kb, vb, ath);

    // O-proj (2-term) + residual(x) -> res fp32; LN1 -> ln1 + hi plane
    gemm_bf<0, false, true, false><<<dim3(mt, 2), 256, SMEM_2T>>>(ath, nullptr, woh, wol, bo, x, res, nullptr, M, DMODEL, DMODEL, 1.f);
    ln_k<true><<<M / 8, 256>>>(res, g1, be1, ln1, l1h);

    // FFN1 (2-term) -> single bf16 (relu); FFN2 (2-term) + residual(ln1) -> res; LN2 -> out
    gemm_bf<1, true,  false, false><<<dim3(mt, 16), 256, SMEM_2T>>>(l1h, nullptr, w1h, w1l, b1, nullptr, fh, nullptr, M, FDIM, DMODEL, 1.f);
    gemm_bf<0, false, true,  false><<<dim3(mt, 2), 256, SMEM_2T>>>(fh, nullptr, w2h, w2l, b2, ln1, res, nullptr, M, DMODEL, FDIM, 1.f);
    ln_k<false><<<M / 8, 256>>>(res, g2, be2, out, nullptr);

    (void)in_sizes; (void)n_in; (void)out_size;
}